// round 9
// baseline (speedup 1.0000x reference)
#include <cuda_runtime.h>
#include <cuda_bf16.h>
#include <math.h>
#include <stdint.h>

// ---- problem constants ----
#define BB   8
#define CC   384
#define LL   1024
#define MM   (BB*LL)
#define NHH  8
#define DKK  48
#define DVV  48
#define CFF_ 1536
#define NBIAS_ 3969
#define LN_EPS_ 1e-5f

typedef __nv_bfloat16 bf16;

// ---- scratch ----
__device__ __align__(16) bf16  g_tok_h [MM*CC], g_tok_l [MM*CC];
__device__ __align__(16) float g_q [MM*CC];                       // [bh][l][d] fp32
__device__ __align__(16) bf16  g_kh[MM*CC], g_kl[MM*CC];          // [bh][key][d]
__device__ __align__(16) bf16  g_vh[MM*CC], g_vl[MM*CC];          // [bh][d][tok]
__device__ __align__(16) bf16  g_attn_h[MM*CC], g_attn_l[MM*CC];
__device__ __align__(16) float g_ytok[MM*CC];
__device__ __align__(16) bf16  g_ytok_h[MM*CC], g_ytok_l[MM*CC];
__device__ __align__(16) bf16  g_u1_h[MM*CFF_], g_u1_l[MM*CFF_];

#define OFF_WQ  0
#define OFF_WK  147456
#define OFF_WV  294912
#define OFF_WO  442368
#define OFF_FC1 589824
#define OFF_FC2 1179648
#define NW_TOTAL 1769472
__device__ __align__(16) bf16 g_w_h[NW_TOTAL], g_w_l[NW_TOTAL];

__device__ __forceinline__ void bsplit(float x, bf16& h, bf16& l) {
    h = __float2bfloat16(x);
    l = __float2bfloat16(x - __bfloat162float(h));
}
__device__ __forceinline__ uint32_t packbf(bf16 a, bf16 b) {
    uint16_t ua = *(uint16_t*)&a, ub = *(uint16_t*)&b;
    return (uint32_t)ua | ((uint32_t)ub << 16);
}

#define MMA_BF16(c, a, b) \
    asm volatile("mma.sync.aligned.m16n8k16.row.col.f32.bf16.bf16.f32 " \
        "{%0,%1,%2,%3}, {%4,%5,%6,%7}, {%8,%9}, {%0,%1,%2,%3};" \
        : "+f"(c[0]), "+f"(c[1]), "+f"(c[2]), "+f"(c[3]) \
        : "r"(a[0]), "r"(a[1]), "r"(a[2]), "r"(a[3]), "r"(b[0]), "r"(b[1]))

// ============================================================
// Single merged weight hi/lo split
// ============================================================
__global__ void split_all(const float* __restrict__ Wq, const float* __restrict__ Wk,
                          const float* __restrict__ Wv, const float* __restrict__ Wo,
                          const float* __restrict__ f1, const float* __restrict__ f2,
                          bf16* __restrict__ h, bf16* __restrict__ l)
{
    int i = blockIdx.x * 256 + threadIdx.x;
    if (i >= NW_TOTAL) return;
    const float* src; int off;
    if (i < OFF_WO) {
        int m = i / 147456; off = i - m * 147456;
        src = (m == 0) ? Wq : (m == 1) ? Wk : Wv;
    } else if (i < OFF_FC1) { src = Wo; off = i - OFF_WO; }
    else if (i < OFF_FC2)   { src = f1; off = i - OFF_FC1; }
    else                    { src = f2; off = i - OFF_FC2; }
    bsplit(src[off], h[i], l[i]);
}

// ============================================================
// LayerNorm -> bf16 hi/lo (unchanged)
// ============================================================
__global__ void ln_kernel(const float* __restrict__ x,
                          const float* __restrict__ gamma,
                          const float* __restrict__ beta,
                          bf16* __restrict__ tok_h, bf16* __restrict__ tok_l)
{
    int b  = blockIdx.y;
    int l0 = blockIdx.x * 32;
    int lane = threadIdx.x;
    int cy   = threadIdx.y;

    __shared__ float redS [8][32];
    __shared__ float redS2[8][32];
    __shared__ float s_mu[32], s_inv[32];
    __shared__ float buf[64][33];

    float s = 0.f, s2 = 0.f;
    for (int c = cy; c < CC; c += 8) {
        float v = x[((size_t)b*CC + c)*LL + l0 + lane];
        s += v; s2 += v*v;
    }
    redS[cy][lane] = s; redS2[cy][lane] = s2;
    __syncthreads();
    if (cy == 0) {
        float ts = 0.f, ts2 = 0.f;
        #pragma unroll
        for (int i = 0; i < 8; i++) { ts += redS[i][lane]; ts2 += redS2[i][lane]; }
        float mu = ts * (1.0f/384.0f);
        float var = ts2 * (1.0f/384.0f) - mu*mu;
        s_mu[lane] = mu;
        s_inv[lane] = rsqrtf(var + LN_EPS_);
    }
    __syncthreads();

    int tid = cy*32 + lane;
    for (int c0 = 0; c0 < CC; c0 += 64) {
        for (int e = tid; e < 64*32; e += 256) {
            int c = e >> 5, t = e & 31;
            buf[c][t] = x[((size_t)b*CC + c0 + c)*LL + l0 + t];
        }
        __syncthreads();
        for (int e = tid; e < 64*32; e += 256) {
            int c = e & 63, t = e >> 6;
            float v = (buf[c][t] - s_mu[t]) * s_inv[t];
            v = v * gamma[c0 + c] + beta[c0 + c];
            size_t idx = ((size_t)b*LL + l0 + t)*CC + c0 + c;
            bf16 hh, ll;
            bsplit(v, hh, ll);
            tok_h[idx] = hh; tok_l[idx] = ll;
        }
        __syncthreads();
    }
}

// ============================================================
// bf16x3 warp-MMA GEMM. MODE 2: fused QKV -> q fp32, K/V pre-split bf16.
// ============================================================
template<int MODE>
__global__ __launch_bounds__(256)
void gemm_bf(const bf16* __restrict__ Ah, const bf16* __restrict__ Al,
             const bf16* __restrict__ Wh, const bf16* __restrict__ Wl,
             const float* __restrict__ bias,
             float* __restrict__ Out,
             int M, int N, int K,
             const float* __restrict__ aux,
             bf16* __restrict__ outH, bf16* __restrict__ outL)
{
    __shared__ uint32_t sAh[128][20], sAl[128][20];
    __shared__ uint32_t sBh[64][20],  sBl[64][20];

    const int tid  = threadIdx.x;
    const int m0   = blockIdx.y * 128;
    const int n0   = blockIdx.x * 64;
    const int warp = tid >> 5, lane = tid & 31;
    const int wm   = (warp >> 1) * 32;
    const int wn   = (warp & 1) * 32;
    const int gk   = lane & 3;
    const int gr   = lane >> 2;

    const int ar = tid >> 1, ak = (tid & 1) * 16;
    const int br = tid >> 2, bk = (tid & 3) * 8;

    const bf16* ApH = Ah + (size_t)(m0 + ar) * K + ak;
    const bf16* ApL = Al + (size_t)(m0 + ar) * K + ak;
    const bf16* BpH = Wh + (size_t)(n0 + br) * K + bk;
    const bf16* BpL = Wl + (size_t)(n0 + br) * K + bk;

    uint4 pah0 = *(const uint4*)ApH;
    uint4 pah1 = *(const uint4*)(ApH + 8);
    uint4 pal0 = *(const uint4*)ApL;
    uint4 pal1 = *(const uint4*)(ApL + 8);
    uint4 pbh  = *(const uint4*)BpH;
    uint4 pbl  = *(const uint4*)BpL;

    float acc[2][4][4];
    #pragma unroll
    for (int mi = 0; mi < 2; mi++)
        #pragma unroll
        for (int nj = 0; nj < 4; nj++)
            #pragma unroll
            for (int r = 0; r < 4; r++) acc[mi][nj][r] = 0.f;

    const int acol = (tid & 1) * 8;
    const int bcol = (tid & 3) * 4;

    for (int k0 = 0; k0 < K; k0 += 32) {
        *(uint4*)&sAh[ar][acol]     = pah0;
        *(uint4*)&sAh[ar][acol + 4] = pah1;
        *(uint4*)&sAl[ar][acol]     = pal0;
        *(uint4*)&sAl[ar][acol + 4] = pal1;
        *(uint4*)&sBh[br][bcol]     = pbh;
        *(uint4*)&sBl[br][bcol]     = pbl;
        __syncthreads();

        if (k0 + 32 < K) {
            ApH += 32; ApL += 32; BpH += 32; BpL += 32;
            pah0 = *(const uint4*)ApH;
            pah1 = *(const uint4*)(ApH + 8);
            pal0 = *(const uint4*)ApL;
            pal1 = *(const uint4*)(ApL + 8);
            pbh  = *(const uint4*)BpH;
            pbl  = *(const uint4*)BpL;
        }

        #pragma unroll
        for (int ks = 0; ks < 2; ks++) {
            const int kb = ks*8 + gk;
            uint32_t ah[2][4], al_[2][4];
            #pragma unroll
            for (int mi = 0; mi < 2; mi++) {
                int mr = wm + mi*16 + gr;
                ah[mi][0]  = sAh[mr    ][kb];
                ah[mi][1]  = sAh[mr + 8][kb];
                ah[mi][2]  = sAh[mr    ][kb + 4];
                ah[mi][3]  = sAh[mr + 8][kb + 4];
                al_[mi][0] = sAl[mr    ][kb];
                al_[mi][1] = sAl[mr + 8][kb];
                al_[mi][2] = sAl[mr    ][kb + 4];
                al_[mi][3] = sAl[mr + 8][kb + 4];
            }
            #pragma unroll
            for (int nj = 0; nj < 4; nj++) {
                int nc = wn + nj*8 + gr;
                uint32_t bh[2], bl[2];
                bh[0] = sBh[nc][kb];
                bh[1] = sBh[nc][kb + 4];
                bl[0] = sBl[nc][kb];
                bl[1] = sBl[nc][kb + 4];
                #pragma unroll
                for (int mi = 0; mi < 2; mi++) {
                    MMA_BF16(acc[mi][nj], ah[mi],  bh);
                    MMA_BF16(acc[mi][nj], al_[mi], bh);
                    MMA_BF16(acc[mi][nj], ah[mi],  bl);
                }
            }
        }
        __syncthreads();
    }

    if (MODE == 2) {
        // fused QKV epilogue: q fp32; K/V split bf16 (K row-major, V transposed)
        uint32_t* kh32 = (uint32_t*)g_kh;
        uint32_t* kl32 = (uint32_t*)g_kl;
        #pragma unroll
        for (int mi = 0; mi < 2; mi++) {
            #pragma unroll
            for (int nj = 0; nj < 4; nj++) {
                int c0  = n0 + wn + nj*8 + 2*gk;
                int mat = c0 / 384;
                int cm  = c0 - mat * 384;
                int hh  = cm / 48, d0 = cm % 48;
                #pragma unroll
                for (int half = 0; half < 2; half++) {
                    int row = m0 + wm + mi*16 + gr + (half ? 8 : 0);
                    int b = row >> 10, l = row & 1023;
                    int bh = b*8 + hh;
                    float v0 = acc[mi][nj][half*2 + 0];
                    float v1 = acc[mi][nj][half*2 + 1];
                    if (mat == 0) {
                        float2 qv = make_float2(v0, v1);
                        *(float2*)&Out[((size_t)bh*1024 + l)*48 + d0] = qv;
                    } else if (mat == 1) {
                        bf16 h0, l0, h1, l1;
                        bsplit(v0, h0, l0); bsplit(v1, h1, l1);
                        size_t i32 = (((size_t)bh*1024 + l)*48 + d0) >> 1;
                        kh32[i32] = packbf(h0, h1);
                        kl32[i32] = packbf(l0, l1);
                    } else {
                        bf16 h0, l0, h1, l1;
                        bsplit(v0, h0, l0); bsplit(v1, h1, l1);
                        size_t base = ((size_t)bh*48 + d0)*1024 + l;
                        g_vh[base] = h0;        g_vl[base] = l0;
                        g_vh[base + 1024] = h1; g_vl[base + 1024] = l1;
                    }
                }
            }
        }
        return;
    }

    #pragma unroll
    for (int mi = 0; mi < 2; mi++) {
        #pragma unroll
        for (int nj = 0; nj < 4; nj++) {
            #pragma unroll
            for (int r = 0; r < 4; r++) {
                int row = m0 + wm + mi*16 + gr + ((r & 2) ? 8 : 0);
                int col = n0 + wn + nj*8 + 2*gk + (r & 1);
                int b = row >> 10, l = row & 1023;
                float v = acc[mi][nj][r] + (bias ? bias[col] : 0.f);
                if (MODE == 3) {
                    v += aux[(size_t)(b*384 + col) * 1024 + l];
                    size_t idx = (size_t)row * 384 + col;
                    Out[idx] = v;
                    bf16 hh, ll;
                    bsplit(v, hh, ll);
                    outH[idx] = hh; outL[idx] = ll;
                } else if (MODE == 1) {
                    v = 0.5f * v * (1.0f + erff(v * 0.70710678118654752f));
                    size_t idx = (size_t)row * N + col;
                    bf16 hh, ll;
                    bsplit(v, hh, ll);
                    outH[idx] = hh; outL[idx] = ll;
                } else { // MODE 4
                    Out[(size_t)(b*384 + col) * 1024 + l] =
                        v + aux[(size_t)row * 384 + col];
                }
            }
        }
    }
}

// ============================================================
// FA2 bf16x3 attention v2: pre-split K/V, uint4 staging,
// exp/pack fused into PV loop, 2 blocks/SM.
// ============================================================
__global__ __launch_bounds__(256, 2)
void attn_mma(const float* __restrict__ q,
              const bf16* __restrict__ khg, const bf16* __restrict__ klg,
              const bf16* __restrict__ vhg, const bf16* __restrict__ vlg,
              const float* __restrict__ rel_bias,
              bf16* __restrict__ attn_h, bf16* __restrict__ attn_l)
{
    const int b  = blockIdx.y >> 3;
    const int h  = blockIdx.y & 7;
    const int bh = b*8 + h;
    const int q0 = blockIdx.x * 128;
    const int tid  = threadIdx.x;
    const int warp = tid >> 5, lane = tid & 31;
    const int gid  = lane >> 2;       // 0..7
    const int tig  = lane & 3;        // 0..3

    __shared__ uint32_t sKh[64][28], sKl[64][28];   // [key][dpair], 16B rows
    __shared__ uint32_t sVh[48][36], sVl[48][36];   // [d][mpair]

    const float* qbase = q + (size_t)bh * LL * 48;
    const uint4* kh4 = (const uint4*)(khg + (size_t)bh * LL * 48);
    const uint4* kl4 = (const uint4*)(klg + (size_t)bh * LL * 48);
    const bf16* vhb = vhg + (size_t)bh * 48 * 1024;
    const bf16* vlb = vlg + (size_t)bh * 48 * 1024;
    const float* biasrow = rel_bias + (size_t)h * NBIAS_;

    const int qrow0 = q0 + warp*16 + gid;
    const int qrow1 = qrow0 + 8;
    const int ly0 = qrow0 >> 5, lx0 = qrow0 & 31;
    const int ly1 = qrow1 >> 5, lx1 = qrow1 & 31;

    // ---- Q fragments (split once) ----
    uint32_t qh[3][4], ql[3][4];
    #pragma unroll
    for (int kp = 0; kp < 3; kp++) {
        int d0 = 16*kp + 2*tig;
        #pragma unroll
        for (int rr = 0; rr < 2; rr++) {
            int row = rr ? qrow1 : qrow0;
            float2 e0 = *(const float2*)&qbase[(size_t)row*48 + d0];
            float2 e1 = *(const float2*)&qbase[(size_t)row*48 + d0 + 8];
            bf16 h0, l0, h1, l1;
            bsplit(e0.x, h0, l0); bsplit(e0.y, h1, l1);
            qh[kp][rr]   = packbf(h0, h1);  ql[kp][rr]   = packbf(l0, l1);
            bsplit(e1.x, h0, l0); bsplit(e1.y, h1, l1);
            qh[kp][rr+2] = packbf(h0, h1);  ql[kp][rr+2] = packbf(l0, l1);
        }
    }

    float m0r = -1e30f, m1r = -1e30f, s0r = 0.f, s1r = 0.f;
    float o[6][4];
    #pragma unroll
    for (int nt = 0; nt < 6; nt++)
        #pragma unroll
        for (int r = 0; r < 4; r++) o[nt][r] = 0.f;

    for (int mc = 0; mc < LL; mc += 64) {
        __syncthreads();

        // ---- stage K (6 uint4/row) + V (8 uint4/row) ----
        for (int e = tid; e < 384; e += 256) {
            int r = e / 6, j = e - r*6;
            *(uint4*)&sKh[r][4*j] = kh4[(size_t)(mc + r)*6 + j];
            *(uint4*)&sKl[r][4*j] = kl4[(size_t)(mc + r)*6 + j];
        }
        for (int e = tid; e < 384; e += 256) {
            int d = e >> 3, j = e & 7;
            *(uint4*)&sVh[d][4*j] = *((const uint4*)(vhb + (size_t)d*1024 + mc) + j);
            *(uint4*)&sVl[d][4*j] = *((const uint4*)(vlb + (size_t)d*1024 + mc) + j);
        }
        __syncthreads();

        // ---- S = Q K^T (bf16x3) ----
        float sc[8][4];
        #pragma unroll
        for (int t = 0; t < 8; t++)
            #pragma unroll
            for (int r = 0; r < 4; r++) sc[t][r] = 0.f;

        #pragma unroll
        for (int kp = 0; kp < 3; kp++) {
            #pragma unroll
            for (int t = 0; t < 8; t++) {
                int key = 8*t + gid;
                int dp  = 8*kp + tig;
                uint32_t bhf[2] = { sKh[key][dp], sKh[key][dp + 4] };
                uint32_t blf[2] = { sKl[key][dp], sKl[key][dp + 4] };
                MMA_BF16(sc[t], qh[kp], bhf);
                MMA_BF16(sc[t], ql[kp], bhf);
                MMA_BF16(sc[t], qh[kp], blf);
            }
        }

        // ---- bias + row max ----
        float rm0 = -1e30f, rm1 = -1e30f;
        #pragma unroll
        for (int t = 0; t < 8; t++) {
            int ma = mc + 8*t + 2*tig, mb = ma + 1;
            int may = ma >> 5, max_ = ma & 31;
            int mby = mb >> 5, mbx = mb & 31;
            sc[t][0] += biasrow[(may - ly0 + 32)*32 + (max_ - lx0 + 32)];
            sc[t][1] += biasrow[(mby - ly0 + 32)*32 + (mbx - lx0 + 32)];
            sc[t][2] += biasrow[(may - ly1 + 32)*32 + (max_ - lx1 + 32)];
            sc[t][3] += biasrow[(mby - ly1 + 32)*32 + (mbx - lx1 + 32)];
            rm0 = fmaxf(rm0, fmaxf(sc[t][0], sc[t][1]));
            rm1 = fmaxf(rm1, fmaxf(sc[t][2], sc[t][3]));
        }
        rm0 = fmaxf(rm0, __shfl_xor_sync(0xffffffffu, rm0, 1));
        rm0 = fmaxf(rm0, __shfl_xor_sync(0xffffffffu, rm0, 2));
        rm1 = fmaxf(rm1, __shfl_xor_sync(0xffffffffu, rm1, 1));
        rm1 = fmaxf(rm1, __shfl_xor_sync(0xffffffffu, rm1, 2));

        float nm0 = fmaxf(m0r, rm0), nm1 = fmaxf(m1r, rm1);
        float al0 = __expf(m0r - nm0), al1 = __expf(m1r - nm1);
        m0r = nm0; m1r = nm1;

        #pragma unroll
        for (int nt = 0; nt < 6; nt++) {
            o[nt][0] *= al0; o[nt][1] *= al0;
            o[nt][2] *= al1; o[nt][3] *= al1;
        }

        // ---- fused exp/pack + PV (bf16x3) ----
        float ps0 = 0.f, ps1 = 0.f;
        #pragma unroll
        for (int kp = 0; kp < 4; kp++) {
            uint32_t ah[4], alo[4];
            #pragma unroll
            for (int tt = 0; tt < 2; tt++) {
                int t = 2*kp + tt;
                float p0 = __expf(sc[t][0] - nm0);
                float p1 = __expf(sc[t][1] - nm0);
                float p2 = __expf(sc[t][2] - nm1);
                float p3 = __expf(sc[t][3] - nm1);
                ps0 += p0 + p1; ps1 += p2 + p3;
                bf16 h0, l0, h1, l1;
                bsplit(p0, h0, l0); bsplit(p1, h1, l1);
                ah[2*tt]  = packbf(h0, h1);  alo[2*tt]  = packbf(l0, l1);
                bsplit(p2, h0, l0); bsplit(p3, h1, l1);
                ah[2*tt+1] = packbf(h0, h1); alo[2*tt+1] = packbf(l0, l1);
            }
            #pragma unroll
            for (int nt = 0; nt < 6; nt++) {
                int d  = 8*nt + gid;
                int mp = 8*kp + tig;
                uint32_t bhf[2] = { sVh[d][mp], sVh[d][mp + 4] };
                uint32_t blf[2] = { sVl[d][mp], sVl[d][mp + 4] };
                MMA_BF16(o[nt], ah,  bhf);
                MMA_BF16(o[nt], alo, bhf);
                MMA_BF16(o[nt], ah,  blf);
            }
        }
        ps0 += __shfl_xor_sync(0xffffffffu, ps0, 1);
        ps0 += __shfl_xor_sync(0xffffffffu, ps0, 2);
        ps1 += __shfl_xor_sync(0xffffffffu, ps1, 1);
        ps1 += __shfl_xor_sync(0xffffffffu, ps1, 2);
        s0r = s0r * al0 + ps0;
        s1r = s1r * al1 + ps1;
    }

    // ---- epilogue ----
    float inv0 = 1.0f / s0r, inv1 = 1.0f / s1r;
    uint32_t* outh32 = (uint32_t*)attn_h;
    uint32_t* outl32 = (uint32_t*)attn_l;
    #pragma unroll
    for (int nt = 0; nt < 6; nt++) {
        int d = 8*nt + 2*tig;
        size_t i0 = ((size_t)(b*LL + qrow0) * 384 + h*48 + d) >> 1;
        size_t i1 = ((size_t)(b*LL + qrow1) * 384 + h*48 + d) >> 1;
        bf16 h0, l0, h1, l1;
        bsplit(o[nt][0]*inv0, h0, l0); bsplit(o[nt][1]*inv0, h1, l1);
        outh32[i0] = packbf(h0, h1);   outl32[i0] = packbf(l0, l1);
        bsplit(o[nt][2]*inv1, h0, l0); bsplit(o[nt][3]*inv1, h1, l1);
        outh32[i1] = packbf(h0, h1);   outl32[i1] = packbf(l0, l1);
    }
}

// ============================================================
// launch
// ============================================================
extern "C" void kernel_launch(void* const* d_in, const int* in_sizes, int n_in,
                              void* d_out, int out_size)
{
    (void)in_sizes; (void)n_in; (void)out_size;
    const float* x        = (const float*)d_in[0];
    const float* gamma    = (const float*)d_in[1];
    const float* beta     = (const float*)d_in[2];
    const float* Wq       = (const float*)d_in[3];
    const float* Wk       = (const float*)d_in[4];
    const float* Wv       = (const float*)d_in[5];
    const float* Wo       = (const float*)d_in[6];
    const float* bo       = (const float*)d_in[7];
    const float* rel_bias = (const float*)d_in[8];
    const float* fc1_w    = (const float*)d_in[9];
    const float* fc1_b    = (const float*)d_in[10];
    const float* fc2_w    = (const float*)d_in[11];
    const float* fc2_b    = (const float*)d_in[12];
    float* out = (float*)d_out;

    bf16 *tok_h, *tok_l, *attn_h, *attn_l, *ytok_h, *ytok_l, *u1_h, *u1_l, *w_h, *w_l;
    bf16 *kh, *kl, *vh, *vl;
    float *q, *ytok;
    cudaGetSymbolAddress((void**)&tok_h,  g_tok_h);
    cudaGetSymbolAddress((void**)&tok_l,  g_tok_l);
    cudaGetSymbolAddress((void**)&q,      g_q);
    cudaGetSymbolAddress((void**)&kh,     g_kh);
    cudaGetSymbolAddress((void**)&kl,     g_kl);
    cudaGetSymbolAddress((void**)&vh,     g_vh);
    cudaGetSymbolAddress((void**)&vl,     g_vl);
    cudaGetSymbolAddress((void**)&attn_h, g_attn_h);
    cudaGetSymbolAddress((void**)&attn_l, g_attn_l);
    cudaGetSymbolAddress((void**)&ytok,   g_ytok);
    cudaGetSymbolAddress((void**)&ytok_h, g_ytok_h);
    cudaGetSymbolAddress((void**)&ytok_l, g_ytok_l);
    cudaGetSymbolAddress((void**)&u1_h,   g_u1_h);
    cudaGetSymbolAddress((void**)&u1_l,   g_u1_l);
    cudaGetSymbolAddress((void**)&w_h,    g_w_h);
    cudaGetSymbolAddress((void**)&w_l,    g_w_l);

    const int M = MM;

    split_all<<<(NW_TOTAL + 255)/256, 256>>>(Wq, Wk, Wv, Wo, fc1_w, fc2_w, w_h, w_l);

    ln_kernel<<<dim3(LL/32, BB), dim3(32, 8)>>>(x, gamma, beta, tok_h, tok_l);

    // fused QKV: N = 1152; writes q fp32 + K/V pre-split bf16
    gemm_bf<2><<<dim3(1152/64, M/128), 256>>>(tok_h, tok_l, w_h+OFF_WQ, w_l+OFF_WQ,
                                              nullptr, q, M, 1152, 384, nullptr, nullptr, nullptr);

    attn_mma<<<dim3(LL/128, BB*NHH), 256>>>(q, kh, kl, vh, vl, rel_bias, attn_h, attn_l);

    gemm_bf<3><<<dim3(384/64,  M/128), 256>>>(attn_h, attn_l, w_h+OFF_WO, w_l+OFF_WO,
                                              bo, ytok, M, 384, 384, x, ytok_h, ytok_l);
    gemm_bf<1><<<dim3(1536/64, M/128), 256>>>(ytok_h, ytok_l, w_h+OFF_FC1, w_l+OFF_FC1,
                                              fc1_b, nullptr, M, 1536, 384, nullptr, u1_h, u1_l);
    gemm_bf<4><<<dim3(384/64,  M/128), 256>>>(u1_h, u1_l, w_h+OFF_FC2, w_l+OFF_FC2,
                                              fc2_b, out, M, 384, 1536, ytok, nullptr, nullptr);
}

// round 10
// speedup vs baseline: 1.5160x; 1.5160x over previous
#include <cuda_runtime.h>
#include <cuda_bf16.h>
#include <math.h>
#include <stdint.h>

// ---- problem constants ----
#define BB   8
#define CC   384
#define LL   1024
#define MM   (BB*LL)
#define NHH  8
#define DKK  48
#define DVV  48
#define CFF_ 1536
#define NBIAS_ 3969
#define LN_EPS_ 1e-5f

typedef __nv_bfloat16 bf16;

// ---- scratch ----
__device__ __align__(16) bf16  g_tok_h [MM*CC], g_tok_l [MM*CC];
__device__ __align__(16) float g_qkv[3*MM*CC];                    // q|k|v, [mat][bh][l][d]
__device__ __align__(16) bf16  g_kh[MM*CC], g_kl[MM*CC];          // [bh][key][d]
__device__ __align__(16) bf16  g_vh[MM*CC], g_vl[MM*CC];          // [bh][d][tok]
__device__ __align__(16) bf16  g_attn_h[MM*CC], g_attn_l[MM*CC];
__device__ __align__(16) float g_ytok[MM*CC];
__device__ __align__(16) bf16  g_ytok_h[MM*CC], g_ytok_l[MM*CC];
__device__ __align__(16) bf16  g_u1_h[MM*CFF_], g_u1_l[MM*CFF_];

#define OFF_WQ  0
#define OFF_WK  147456
#define OFF_WV  294912
#define OFF_WO  442368
#define OFF_FC1 589824
#define OFF_FC2 1179648
#define NW_TOTAL 1769472
__device__ __align__(16) bf16 g_w_h[NW_TOTAL], g_w_l[NW_TOTAL];

__device__ __forceinline__ void bsplit(float x, bf16& h, bf16& l) {
    h = __float2bfloat16(x);
    l = __float2bfloat16(x - __bfloat162float(h));
}
__device__ __forceinline__ uint32_t packbf(bf16 a, bf16 b) {
    uint16_t ua = *(uint16_t*)&a, ub = *(uint16_t*)&b;
    return (uint32_t)ua | ((uint32_t)ub << 16);
}

#define MMA_BF16(c, a, b) \
    asm volatile("mma.sync.aligned.m16n8k16.row.col.f32.bf16.bf16.f32 " \
        "{%0,%1,%2,%3}, {%4,%5,%6,%7}, {%8,%9}, {%0,%1,%2,%3};" \
        : "+f"(c[0]), "+f"(c[1]), "+f"(c[2]), "+f"(c[3]) \
        : "r"(a[0]), "r"(a[1]), "r"(a[2]), "r"(a[3]), "r"(b[0]), "r"(b[1]))

// ============================================================
// Single merged weight hi/lo split
// ============================================================
__global__ void split_all(const float* __restrict__ Wq, const float* __restrict__ Wk,
                          const float* __restrict__ Wv, const float* __restrict__ Wo,
                          const float* __restrict__ f1, const float* __restrict__ f2,
                          bf16* __restrict__ h, bf16* __restrict__ l)
{
    int i = blockIdx.x * 256 + threadIdx.x;
    if (i >= NW_TOTAL) return;
    const float* src; int off;
    if (i < OFF_WO) {
        int m = i / 147456; off = i - m * 147456;
        src = (m == 0) ? Wq : (m == 1) ? Wk : Wv;
    } else if (i < OFF_FC1) { src = Wo; off = i - OFF_WO; }
    else if (i < OFF_FC2)   { src = f1; off = i - OFF_FC1; }
    else                    { src = f2; off = i - OFF_FC2; }
    bsplit(src[off], h[i], l[i]);
}

// ============================================================
// K/V prep: coalesced split (K) and transpose+split (V).
// grid (LL/64, B*NH), block 256.
// ============================================================
__global__ void kv_prep(const float* __restrict__ kin, const float* __restrict__ vin,
                        bf16* __restrict__ kh, bf16* __restrict__ kl,
                        bf16* __restrict__ vh, bf16* __restrict__ vl)
{
    const int bh = blockIdx.y;
    const int l0 = blockIdx.x * 64;
    const int tid = threadIdx.x;
    __shared__ float sv[48][65];

    const float* kb = kin + ((size_t)bh*1024 + l0)*48;
    const float* vb = vin + ((size_t)bh*1024 + l0)*48;
    uint32_t* kh32 = (uint32_t*)(kh + ((size_t)bh*1024 + l0)*48);
    uint32_t* kl32 = (uint32_t*)(kl + ((size_t)bh*1024 + l0)*48);

    // K: 1536 element-pairs, coalesced in and out
    for (int e = tid; e < 1536; e += 256) {
        float2 p = *(const float2*)&kb[2*e];
        bf16 h0, lo0, h1, lo1;
        bsplit(p.x, h0, lo0); bsplit(p.y, h1, lo1);
        kh32[e] = packbf(h0, h1);
        kl32[e] = packbf(lo0, lo1);
    }

    // V: stage transposed in smem (coalesced read), write along l (coalesced)
    for (int e = tid; e < 3072; e += 256) {
        int l = e / 48, d = e % 48;
        sv[d][l] = vb[e];
    }
    __syncthreads();
    uint32_t* vh32 = (uint32_t*)vh;
    uint32_t* vl32 = (uint32_t*)vl;
    for (int e = tid; e < 1536; e += 256) {
        int d = e >> 5, lp = e & 31;
        bf16 h0, lo0, h1, lo1;
        bsplit(sv[d][2*lp],     h0, lo0);
        bsplit(sv[d][2*lp + 1], h1, lo1);
        size_t i32 = ((((size_t)bh*48 + d)*1024 + l0) >> 1) + lp;
        vh32[i32] = packbf(h0, h1);
        vl32[i32] = packbf(lo0, lo1);
    }
}

// ============================================================
// LayerNorm -> bf16 hi/lo (unchanged)
// ============================================================
__global__ void ln_kernel(const float* __restrict__ x,
                          const float* __restrict__ gamma,
                          const float* __restrict__ beta,
                          bf16* __restrict__ tok_h, bf16* __restrict__ tok_l)
{
    int b  = blockIdx.y;
    int l0 = blockIdx.x * 32;
    int lane = threadIdx.x;
    int cy   = threadIdx.y;

    __shared__ float redS [8][32];
    __shared__ float redS2[8][32];
    __shared__ float s_mu[32], s_inv[32];
    __shared__ float buf[64][33];

    float s = 0.f, s2 = 0.f;
    for (int c = cy; c < CC; c += 8) {
        float v = x[((size_t)b*CC + c)*LL + l0 + lane];
        s += v; s2 += v*v;
    }
    redS[cy][lane] = s; redS2[cy][lane] = s2;
    __syncthreads();
    if (cy == 0) {
        float ts = 0.f, ts2 = 0.f;
        #pragma unroll
        for (int i = 0; i < 8; i++) { ts += redS[i][lane]; ts2 += redS2[i][lane]; }
        float mu = ts * (1.0f/384.0f);
        float var = ts2 * (1.0f/384.0f) - mu*mu;
        s_mu[lane] = mu;
        s_inv[lane] = rsqrtf(var + LN_EPS_);
    }
    __syncthreads();

    int tid = cy*32 + lane;
    for (int c0 = 0; c0 < CC; c0 += 64) {
        for (int e = tid; e < 64*32; e += 256) {
            int c = e >> 5, t = e & 31;
            buf[c][t] = x[((size_t)b*CC + c0 + c)*LL + l0 + t];
        }
        __syncthreads();
        for (int e = tid; e < 64*32; e += 256) {
            int c = e & 63, t = e >> 6;
            float v = (buf[c][t] - s_mu[t]) * s_inv[t];
            v = v * gamma[c0 + c] + beta[c0 + c];
            size_t idx = ((size_t)b*LL + l0 + t)*CC + c0 + c;
            bf16 hh, ll;
            bsplit(v, hh, ll);
            tok_h[idx] = hh; tok_l[idx] = ll;
        }
        __syncthreads();
    }
}

// ============================================================
// bf16x3 warp-MMA GEMM. MODE 2: fused QKV -> fp32 head-scatter (round-8).
// ============================================================
template<int MODE>
__global__ __launch_bounds__(256)
void gemm_bf(const bf16* __restrict__ Ah, const bf16* __restrict__ Al,
             const bf16* __restrict__ Wh, const bf16* __restrict__ Wl,
             const float* __restrict__ bias,
             float* __restrict__ Out,
             int M, int N, int K,
             const float* __restrict__ aux,
             bf16* __restrict__ outH, bf16* __restrict__ outL)
{
    __shared__ uint32_t sAh[128][20], sAl[128][20];
    __shared__ uint32_t sBh[64][20],  sBl[64][20];

    const int tid  = threadIdx.x;
    const int m0   = blockIdx.y * 128;
    const int n0   = blockIdx.x * 64;
    const int warp = tid >> 5, lane = tid & 31;
    const int wm   = (warp >> 1) * 32;
    const int wn   = (warp & 1) * 32;
    const int gk   = lane & 3;
    const int gr   = lane >> 2;

    const int ar = tid >> 1, ak = (tid & 1) * 16;
    const int br = tid >> 2, bk = (tid & 3) * 8;

    const bf16* ApH = Ah + (size_t)(m0 + ar) * K + ak;
    const bf16* ApL = Al + (size_t)(m0 + ar) * K + ak;
    const bf16* BpH = Wh + (size_t)(n0 + br) * K + bk;
    const bf16* BpL = Wl + (size_t)(n0 + br) * K + bk;

    uint4 pah0 = *(const uint4*)ApH;
    uint4 pah1 = *(const uint4*)(ApH + 8);
    uint4 pal0 = *(const uint4*)ApL;
    uint4 pal1 = *(const uint4*)(ApL + 8);
    uint4 pbh  = *(const uint4*)BpH;
    uint4 pbl  = *(const uint4*)BpL;

    float acc[2][4][4];
    #pragma unroll
    for (int mi = 0; mi < 2; mi++)
        #pragma unroll
        for (int nj = 0; nj < 4; nj++)
            #pragma unroll
            for (int r = 0; r < 4; r++) acc[mi][nj][r] = 0.f;

    const int acol = (tid & 1) * 8;
    const int bcol = (tid & 3) * 4;

    for (int k0 = 0; k0 < K; k0 += 32) {
        *(uint4*)&sAh[ar][acol]     = pah0;
        *(uint4*)&sAh[ar][acol + 4] = pah1;
        *(uint4*)&sAl[ar][acol]     = pal0;
        *(uint4*)&sAl[ar][acol + 4] = pal1;
        *(uint4*)&sBh[br][bcol]     = pbh;
        *(uint4*)&sBl[br][bcol]     = pbl;
        __syncthreads();

        if (k0 + 32 < K) {
            ApH += 32; ApL += 32; BpH += 32; BpL += 32;
            pah0 = *(const uint4*)ApH;
            pah1 = *(const uint4*)(ApH + 8);
            pal0 = *(const uint4*)ApL;
            pal1 = *(const uint4*)(ApL + 8);
            pbh  = *(const uint4*)BpH;
            pbl  = *(const uint4*)BpL;
        }

        #pragma unroll
        for (int ks = 0; ks < 2; ks++) {
            const int kb = ks*8 + gk;
            uint32_t ah[2][4], al_[2][4];
            #pragma unroll
            for (int mi = 0; mi < 2; mi++) {
                int mr = wm + mi*16 + gr;
                ah[mi][0]  = sAh[mr    ][kb];
                ah[mi][1]  = sAh[mr + 8][kb];
                ah[mi][2]  = sAh[mr    ][kb + 4];
                ah[mi][3]  = sAh[mr + 8][kb + 4];
                al_[mi][0] = sAl[mr    ][kb];
                al_[mi][1] = sAl[mr + 8][kb];
                al_[mi][2] = sAl[mr    ][kb + 4];
                al_[mi][3] = sAl[mr + 8][kb + 4];
            }
            #pragma unroll
            for (int nj = 0; nj < 4; nj++) {
                int nc = wn + nj*8 + gr;
                uint32_t bh[2], bl[2];
                bh[0] = sBh[nc][kb];
                bh[1] = sBh[nc][kb + 4];
                bl[0] = sBl[nc][kb];
                bl[1] = sBl[nc][kb + 4];
                #pragma unroll
                for (int mi = 0; mi < 2; mi++) {
                    MMA_BF16(acc[mi][nj], ah[mi],  bh);
                    MMA_BF16(acc[mi][nj], al_[mi], bh);
                    MMA_BF16(acc[mi][nj], ah[mi],  bl);
                }
            }
        }
        __syncthreads();
    }

    #pragma unroll
    for (int mi = 0; mi < 2; mi++) {
        #pragma unroll
        for (int nj = 0; nj < 4; nj++) {
            #pragma unroll
            for (int r = 0; r < 4; r++) {
                int row = m0 + wm + mi*16 + gr + ((r & 2) ? 8 : 0);
                int col = n0 + wn + nj*8 + 2*gk + (r & 1);
                int b = row >> 10, l = row & 1023;
                float v = acc[mi][nj][r] + (bias ? bias[col] : 0.f);
                if (MODE == 2) {
                    // fused QKV: col in [0,1152), fp32 head-scatter
                    int mat = col / 384;
                    int cm  = col - mat * 384;
                    int h = cm / 48, d = cm % 48;
                    Out[(size_t)mat * (MM*CC)
                        + (size_t)(((b*8 + h) * 1024) + l) * 48 + d] = v;
                } else if (MODE == 3) {
                    v += aux[(size_t)(b*384 + col) * 1024 + l];
                    size_t idx = (size_t)row * 384 + col;
                    Out[idx] = v;
                    bf16 hh, ll;
                    bsplit(v, hh, ll);
                    outH[idx] = hh; outL[idx] = ll;
                } else if (MODE == 1) {
                    v = 0.5f * v * (1.0f + erff(v * 0.70710678118654752f));
                    size_t idx = (size_t)row * N + col;
                    bf16 hh, ll;
                    bsplit(v, hh, ll);
                    outH[idx] = hh; outL[idx] = ll;
                } else { // MODE 4
                    Out[(size_t)(b*384 + col) * 1024 + l] =
                        v + aux[(size_t)row * 384 + col];
                }
            }
        }
    }
}

// ============================================================
// FA2 bf16x3 attention (round-9 version, measured 289us)
// ============================================================
__global__ __launch_bounds__(256, 2)
void attn_mma(const float* __restrict__ q,
              const bf16* __restrict__ khg, const bf16* __restrict__ klg,
              const bf16* __restrict__ vhg, const bf16* __restrict__ vlg,
              const float* __restrict__ rel_bias,
              bf16* __restrict__ attn_h, bf16* __restrict__ attn_l)
{
    const int b  = blockIdx.y >> 3;
    const int h  = blockIdx.y & 7;
    const int bh = b*8 + h;
    const int q0 = blockIdx.x * 128;
    const int tid  = threadIdx.x;
    const int warp = tid >> 5, lane = tid & 31;
    const int gid  = lane >> 2;
    const int tig  = lane & 3;

    __shared__ uint32_t sKh[64][28], sKl[64][28];
    __shared__ uint32_t sVh[48][36], sVl[48][36];

    const float* qbase = q + (size_t)bh * LL * 48;
    const uint4* kh4 = (const uint4*)(khg + (size_t)bh * LL * 48);
    const uint4* kl4 = (const uint4*)(klg + (size_t)bh * LL * 48);
    const bf16* vhb = vhg + (size_t)bh * 48 * 1024;
    const bf16* vlb = vlg + (size_t)bh * 48 * 1024;
    const float* biasrow = rel_bias + (size_t)h * NBIAS_;

    const int qrow0 = q0 + warp*16 + gid;
    const int qrow1 = qrow0 + 8;
    const int ly0 = qrow0 >> 5, lx0 = qrow0 & 31;
    const int ly1 = qrow1 >> 5, lx1 = qrow1 & 31;

    uint32_t qh[3][4], ql[3][4];
    #pragma unroll
    for (int kp = 0; kp < 3; kp++) {
        int d0 = 16*kp + 2*tig;
        #pragma unroll
        for (int rr = 0; rr < 2; rr++) {
            int row = rr ? qrow1 : qrow0;
            float2 e0 = *(const float2*)&qbase[(size_t)row*48 + d0];
            float2 e1 = *(const float2*)&qbase[(size_t)row*48 + d0 + 8];
            bf16 h0, l0, h1, l1;
            bsplit(e0.x, h0, l0); bsplit(e0.y, h1, l1);
            qh[kp][rr]   = packbf(h0, h1);  ql[kp][rr]   = packbf(l0, l1);
            bsplit(e1.x, h0, l0); bsplit(e1.y, h1, l1);
            qh[kp][rr+2] = packbf(h0, h1);  ql[kp][rr+2] = packbf(l0, l1);
        }
    }

    float m0r = -1e30f, m1r = -1e30f, s0r = 0.f, s1r = 0.f;
    float o[6][4];
    #pragma unroll
    for (int nt = 0; nt < 6; nt++)
        #pragma unroll
        for (int r = 0; r < 4; r++) o[nt][r] = 0.f;

    for (int mc = 0; mc < LL; mc += 64) {
        __syncthreads();

        for (int e = tid; e < 384; e += 256) {
            int r = e / 6, j = e - r*6;
            *(uint4*)&sKh[r][4*j] = kh4[(size_t)(mc + r)*6 + j];
            *(uint4*)&sKl[r][4*j] = kl4[(size_t)(mc + r)*6 + j];
        }
        for (int e = tid; e < 384; e += 256) {
            int d = e >> 3, j = e & 7;
            *(uint4*)&sVh[d][4*j] = *((const uint4*)(vhb + (size_t)d*1024 + mc) + j);
            *(uint4*)&sVl[d][4*j] = *((const uint4*)(vlb + (size_t)d*1024 + mc) + j);
        }
        __syncthreads();

        float sc[8][4];
        #pragma unroll
        for (int t = 0; t < 8; t++)
            #pragma unroll
            for (int r = 0; r < 4; r++) sc[t][r] = 0.f;

        #pragma unroll
        for (int kp = 0; kp < 3; kp++) {
            #pragma unroll
            for (int t = 0; t < 8; t++) {
                int key = 8*t + gid;
                int dp  = 8*kp + tig;
                uint32_t bhf[2] = { sKh[key][dp], sKh[key][dp + 4] };
                uint32_t blf[2] = { sKl[key][dp], sKl[key][dp + 4] };
                MMA_BF16(sc[t], qh[kp], bhf);
                MMA_BF16(sc[t], ql[kp], bhf);
                MMA_BF16(sc[t], qh[kp], blf);
            }
        }

        float rm0 = -1e30f, rm1 = -1e30f;
        #pragma unroll
        for (int t = 0; t < 8; t++) {
            int ma = mc + 8*t + 2*tig, mb = ma + 1;
            int may = ma >> 5, max_ = ma & 31;
            int mby = mb >> 5, mbx = mb & 31;
            sc[t][0] += biasrow[(may - ly0 + 32)*32 + (max_ - lx0 + 32)];
            sc[t][1] += biasrow[(mby - ly0 + 32)*32 + (mbx - lx0 + 32)];
            sc[t][2] += biasrow[(may - ly1 + 32)*32 + (max_ - lx1 + 32)];
            sc[t][3] += biasrow[(mby - ly1 + 32)*32 + (mbx - lx1 + 32)];
            rm0 = fmaxf(rm0, fmaxf(sc[t][0], sc[t][1]));
            rm1 = fmaxf(rm1, fmaxf(sc[t][2], sc[t][3]));
        }
        rm0 = fmaxf(rm0, __shfl_xor_sync(0xffffffffu, rm0, 1));
        rm0 = fmaxf(rm0, __shfl_xor_sync(0xffffffffu, rm0, 2));
        rm1 = fmaxf(rm1, __shfl_xor_sync(0xffffffffu, rm1, 1));
        rm1 = fmaxf(rm1, __shfl_xor_sync(0xffffffffu, rm1, 2));

        float nm0 = fmaxf(m0r, rm0), nm1 = fmaxf(m1r, rm1);
        float al0 = __expf(m0r - nm0), al1 = __expf(m1r - nm1);
        m0r = nm0; m1r = nm1;

        #pragma unroll
        for (int nt = 0; nt < 6; nt++) {
            o[nt][0] *= al0; o[nt][1] *= al0;
            o[nt][2] *= al1; o[nt][3] *= al1;
        }

        float ps0 = 0.f, ps1 = 0.f;
        #pragma unroll
        for (int kp = 0; kp < 4; kp++) {
            uint32_t ah[4], alo[4];
            #pragma unroll
            for (int tt = 0; tt < 2; tt++) {
                int t = 2*kp + tt;
                float p0 = __expf(sc[t][0] - nm0);
                float p1 = __expf(sc[t][1] - nm0);
                float p2 = __expf(sc[t][2] - nm1);
                float p3 = __expf(sc[t][3] - nm1);
                ps0 += p0 + p1; ps1 += p2 + p3;
                bf16 h0, l0, h1, l1;
                bsplit(p0, h0, l0); bsplit(p1, h1, l1);
                ah[2*tt]  = packbf(h0, h1);  alo[2*tt]  = packbf(l0, l1);
                bsplit(p2, h0, l0); bsplit(p3, h1, l1);
                ah[2*tt+1] = packbf(h0, h1); alo[2*tt+1] = packbf(l0, l1);
            }
            #pragma unroll
            for (int nt = 0; nt < 6; nt++) {
                int d  = 8*nt + gid;
                int mp = 8*kp + tig;
                uint32_t bhf[2] = { sVh[d][mp], sVh[d][mp + 4] };
                uint32_t blf[2] = { sVl[d][mp], sVl[d][mp + 4] };
                MMA_BF16(o[nt], ah,  bhf);
                MMA_BF16(o[nt], alo, bhf);
                MMA_BF16(o[nt], ah,  blf);
            }
        }
        ps0 += __shfl_xor_sync(0xffffffffu, ps0, 1);
        ps0 += __shfl_xor_sync(0xffffffffu, ps0, 2);
        ps1 += __shfl_xor_sync(0xffffffffu, ps1, 1);
        ps1 += __shfl_xor_sync(0xffffffffu, ps1, 2);
        s0r = s0r * al0 + ps0;
        s1r = s1r * al1 + ps1;
    }

    float inv0 = 1.0f / s0r, inv1 = 1.0f / s1r;
    uint32_t* outh32 = (uint32_t*)attn_h;
    uint32_t* outl32 = (uint32_t*)attn_l;
    #pragma unroll
    for (int nt = 0; nt < 6; nt++) {
        int d = 8*nt + 2*tig;
        size_t i0 = ((size_t)(b*LL + qrow0) * 384 + h*48 + d) >> 1;
        size_t i1 = ((size_t)(b*LL + qrow1) * 384 + h*48 + d) >> 1;
        bf16 h0, l0, h1, l1;
        bsplit(o[nt][0]*inv0, h0, l0); bsplit(o[nt][1]*inv0, h1, l1);
        outh32[i0] = packbf(h0, h1);   outl32[i0] = packbf(l0, l1);
        bsplit(o[nt][2]*inv1, h0, l0); bsplit(o[nt][3]*inv1, h1, l1);
        outh32[i1] = packbf(h0, h1);   outl32[i1] = packbf(l0, l1);
    }
}

// ============================================================
// launch
// ============================================================
extern "C" void kernel_launch(void* const* d_in, const int* in_sizes, int n_in,
                              void* d_out, int out_size)
{
    (void)in_sizes; (void)n_in; (void)out_size;
    const float* x        = (const float*)d_in[0];
    const float* gamma    = (const float*)d_in[1];
    const float* beta     = (const float*)d_in[2];
    const float* Wq       = (const float*)d_in[3];
    const float* Wk       = (const float*)d_in[4];
    const float* Wv       = (const float*)d_in[5];
    const float* Wo       = (const float*)d_in[6];
    const float* bo       = (const float*)d_in[7];
    const float* rel_bias = (const float*)d_in[8];
    const float* fc1_w    = (const float*)d_in[9];
    const float* fc1_b    = (const float*)d_in[10];
    const float* fc2_w    = (const float*)d_in[11];
    const float* fc2_b    = (const float*)d_in[12];
    float* out = (float*)d_out;

    bf16 *tok_h, *tok_l, *attn_h, *attn_l, *ytok_h, *ytok_l, *u1_h, *u1_l, *w_h, *w_l;
    bf16 *kh, *kl, *vh, *vl;
    float *qkv, *ytok;
    cudaGetSymbolAddress((void**)&tok_h,  g_tok_h);
    cudaGetSymbolAddress((void**)&tok_l,  g_tok_l);
    cudaGetSymbolAddress((void**)&qkv,    g_qkv);
    cudaGetSymbolAddress((void**)&kh,     g_kh);
    cudaGetSymbolAddress((void**)&kl,     g_kl);
    cudaGetSymbolAddress((void**)&vh,     g_vh);
    cudaGetSymbolAddress((void**)&vl,     g_vl);
    cudaGetSymbolAddress((void**)&attn_h, g_attn_h);
    cudaGetSymbolAddress((void**)&attn_l, g_attn_l);
    cudaGetSymbolAddress((void**)&ytok,   g_ytok);
    cudaGetSymbolAddress((void**)&ytok_h, g_ytok_h);
    cudaGetSymbolAddress((void**)&ytok_l, g_ytok_l);
    cudaGetSymbolAddress((void**)&u1_h,   g_u1_h);
    cudaGetSymbolAddress((void**)&u1_l,   g_u1_l);
    cudaGetSymbolAddress((void**)&w_h,    g_w_h);
    cudaGetSymbolAddress((void**)&w_l,    g_w_l);

    float* q = qkv;
    float* kf = qkv + (size_t)MM*CC;
    float* vf = qkv + 2*(size_t)MM*CC;

    const int M = MM;

    split_all<<<(NW_TOTAL + 255)/256, 256>>>(Wq, Wk, Wv, Wo, fc1_w, fc2_w, w_h, w_l);

    ln_kernel<<<dim3(LL/32, BB), dim3(32, 8)>>>(x, gamma, beta, tok_h, tok_l);

    // fused QKV: fp32 outputs [mat][bh][l][d]
    gemm_bf<2><<<dim3(1152/64, M/128), 256>>>(tok_h, tok_l, w_h+OFF_WQ, w_l+OFF_WQ,
                                              nullptr, qkv, M, 1152, 384, nullptr, nullptr, nullptr);

    // coalesced K/V split + V transpose
    kv_prep<<<dim3(LL/64, BB*NHH), 256>>>(kf, vf, kh, kl, vh, vl);

    attn_mma<<<dim3(LL/128, BB*NHH), 256>>>(q, kh, kl, vh, vl, rel_bias, attn_h, attn_l);

    gemm_bf<3><<<dim3(384/64,  M/128), 256>>>(attn_h, attn_l, w_h+OFF_WO, w_l+OFF_WO,
                                              bo, ytok, M, 384, 384, x, ytok_h, ytok_l);
    gemm_bf<1><<<dim3(1536/64, M/128), 256>>>(ytok_h, ytok_l, w_h+OFF_FC1, w_l+OFF_FC1,
                                              fc1_b, nullptr, M, 1536, 384, nullptr, u1_h, u1_l);
    gemm_bf<4><<<dim3(384/64,  M/128), 256>>>(u1_h, u1_l, w_h+OFF_FC2, w_l+OFF_FC2,
                                              fc2_b, out, M, 384, 1536, ytok, nullptr, nullptr);
}

// round 11
// speedup vs baseline: 2.8953x; 1.9098x over previous
#include <cuda_runtime.h>
#include <cuda_fp16.h>
#include <math.h>
#include <stdint.h>

// ---- problem constants ----
#define BB   8
#define CC   384
#define LL   1024
#define MM   (BB*LL)
#define NHH  8
#define DKK  48
#define DVV  48
#define CFF_ 1536
#define NBIAS_ 3969
#define LN_EPS_ 1e-5f

typedef __half fp16;

// ---- scratch ----
__device__ __align__(16) fp16  g_tok [MM*CC];
__device__ __align__(16) float g_qkv[3*MM*CC];        // q|k|v, [mat][bh][l][d] fp32
__device__ __align__(16) fp16  g_kh[MM*CC];           // [bh][key][d]
__device__ __align__(16) fp16  g_vh[MM*CC];           // [bh][d][tok]
__device__ __align__(16) fp16  g_attn[MM*CC];
__device__ __align__(16) float g_ytok[MM*CC];
__device__ __align__(16) fp16  g_ytokh[MM*CC];
__device__ __align__(16) fp16  g_u1[MM*CFF_];

#define OFF_WQ  0
#define OFF_WK  147456
#define OFF_WV  294912
#define OFF_WO  442368
#define OFF_FC1 589824
#define OFF_FC2 1179648
#define NW_TOTAL 1769472
__device__ __align__(16) fp16 g_w[NW_TOTAL];

__device__ __forceinline__ uint32_t packh(fp16 a, fp16 b) {
    uint16_t ua = *(uint16_t*)&a, ub = *(uint16_t*)&b;
    return (uint32_t)ua | ((uint32_t)ub << 16);
}
__device__ __forceinline__ uint32_t packf(float a, float b) {
    return packh(__float2half(a), __float2half(b));
}

#define MMA_F16(c, a, b) \
    asm volatile("mma.sync.aligned.m16n8k16.row.col.f32.f16.f16.f32 " \
        "{%0,%1,%2,%3}, {%4,%5,%6,%7}, {%8,%9}, {%0,%1,%2,%3};" \
        : "+f"(c[0]), "+f"(c[1]), "+f"(c[2]), "+f"(c[3]) \
        : "r"(a[0]), "r"(a[1]), "r"(a[2]), "r"(a[3]), "r"(b[0]), "r"(b[1]))

// ============================================================
// Merged weight fp16 conversion
// ============================================================
__global__ void conv_all(const float* __restrict__ Wq, const float* __restrict__ Wk,
                         const float* __restrict__ Wv, const float* __restrict__ Wo,
                         const float* __restrict__ f1, const float* __restrict__ f2,
                         fp16* __restrict__ w)
{
    int i = blockIdx.x * 256 + threadIdx.x;
    if (i >= NW_TOTAL) return;
    const float* src; int off;
    if (i < OFF_WO) {
        int m = i / 147456; off = i - m * 147456;
        src = (m == 0) ? Wq : (m == 1) ? Wk : Wv;
    } else if (i < OFF_FC1) { src = Wo; off = i - OFF_WO; }
    else if (i < OFF_FC2)   { src = f1; off = i - OFF_FC1; }
    else                    { src = f2; off = i - OFF_FC2; }
    w[i] = __float2half(src[off]);
}

// ============================================================
// K/V prep: coalesced fp16 convert (K) and transpose+convert (V)
// ============================================================
__global__ void kv_prep(const float* __restrict__ kin, const float* __restrict__ vin,
                        fp16* __restrict__ kh, fp16* __restrict__ vh)
{
    const int bh = blockIdx.y;
    const int l0 = blockIdx.x * 64;
    const int tid = threadIdx.x;
    __shared__ float sv[48][65];

    const float* kb = kin + ((size_t)bh*1024 + l0)*48;
    const float* vb = vin + ((size_t)bh*1024 + l0)*48;
    uint32_t* kh32 = (uint32_t*)(kh + ((size_t)bh*1024 + l0)*48);

    for (int e = tid; e < 1536; e += 256) {
        float2 p = *(const float2*)&kb[2*e];
        kh32[e] = packf(p.x, p.y);
    }

    for (int e = tid; e < 3072; e += 256) {
        int l = e / 48, d = e % 48;
        sv[d][l] = vb[e];
    }
    __syncthreads();
    uint32_t* vh32 = (uint32_t*)vh;
    for (int e = tid; e < 1536; e += 256) {
        int d = e >> 5, lp = e & 31;
        size_t i32 = ((((size_t)bh*48 + d)*1024 + l0) >> 1) + lp;
        vh32[i32] = packf(sv[d][2*lp], sv[d][2*lp + 1]);
    }
}

// ============================================================
// LayerNorm -> fp16 tokens
// ============================================================
__global__ void ln_kernel(const float* __restrict__ x,
                          const float* __restrict__ gamma,
                          const float* __restrict__ beta,
                          fp16* __restrict__ tok)
{
    int b  = blockIdx.y;
    int l0 = blockIdx.x * 32;
    int lane = threadIdx.x;
    int cy   = threadIdx.y;

    __shared__ float redS [8][32];
    __shared__ float redS2[8][32];
    __shared__ float s_mu[32], s_inv[32];
    __shared__ float buf[64][33];

    float s = 0.f, s2 = 0.f;
    for (int c = cy; c < CC; c += 8) {
        float v = x[((size_t)b*CC + c)*LL + l0 + lane];
        s += v; s2 += v*v;
    }
    redS[cy][lane] = s; redS2[cy][lane] = s2;
    __syncthreads();
    if (cy == 0) {
        float ts = 0.f, ts2 = 0.f;
        #pragma unroll
        for (int i = 0; i < 8; i++) { ts += redS[i][lane]; ts2 += redS2[i][lane]; }
        float mu = ts * (1.0f/384.0f);
        float var = ts2 * (1.0f/384.0f) - mu*mu;
        s_mu[lane] = mu;
        s_inv[lane] = rsqrtf(var + LN_EPS_);
    }
    __syncthreads();

    int tid = cy*32 + lane;
    for (int c0 = 0; c0 < CC; c0 += 64) {
        for (int e = tid; e < 64*32; e += 256) {
            int c = e >> 5, t = e & 31;
            buf[c][t] = x[((size_t)b*CC + c0 + c)*LL + l0 + t];
        }
        __syncthreads();
        for (int e = tid; e < 64*32; e += 256) {
            int c = e & 63, t = e >> 6;
            float v = (buf[c][t] - s_mu[t]) * s_inv[t];
            v = v * gamma[c0 + c] + beta[c0 + c];
            tok[((size_t)b*LL + l0 + t)*CC + c0 + c] = __float2half(v);
        }
        __syncthreads();
    }
}

// ============================================================
// fp16 warp-MMA GEMM: Out = A[M,K] * W[N,K]^T (+bias), fp32 accum.
// 128x64 block, 8 warps (4m x 2n), warp tile 32x32, m16n8k16.
// MODE 1: GELU -> fp16 out     MODE 2: fused QKV fp32 head-scatter
// MODE 3: +x residual -> fp32 Out AND fp16 outH
// MODE 4: transposed store + residual (final fp32 output)
// ============================================================
template<int MODE>
__global__ __launch_bounds__(256)
void gemm_f16(const fp16* __restrict__ A,
              const fp16* __restrict__ W,
              const float* __restrict__ bias,
              float* __restrict__ Out,
              int M, int N, int K,
              const float* __restrict__ aux,
              fp16* __restrict__ outH)
{
    __shared__ uint32_t sA[128][20];
    __shared__ uint32_t sB[64][20];

    const int tid  = threadIdx.x;
    const int m0   = blockIdx.y * 128;
    const int n0   = blockIdx.x * 64;
    const int warp = tid >> 5, lane = tid & 31;
    const int wm   = (warp >> 1) * 32;
    const int wn   = (warp & 1) * 32;
    const int gk   = lane & 3;
    const int gr   = lane >> 2;

    const int ar = tid >> 1, ak = (tid & 1) * 16;
    const int br = tid >> 2, bk = (tid & 3) * 8;

    const fp16* Ap = A + (size_t)(m0 + ar) * K + ak;
    const fp16* Bp = W + (size_t)(n0 + br) * K + bk;

    uint4 pa0 = *(const uint4*)Ap;
    uint4 pa1 = *(const uint4*)(Ap + 8);
    uint4 pb  = *(const uint4*)Bp;

    float acc[2][4][4];
    #pragma unroll
    for (int mi = 0; mi < 2; mi++)
        #pragma unroll
        for (int nj = 0; nj < 4; nj++)
            #pragma unroll
            for (int r = 0; r < 4; r++) acc[mi][nj][r] = 0.f;

    const int acol = (tid & 1) * 8;
    const int bcol = (tid & 3) * 4;

    for (int k0 = 0; k0 < K; k0 += 32) {
        *(uint4*)&sA[ar][acol]     = pa0;
        *(uint4*)&sA[ar][acol + 4] = pa1;
        *(uint4*)&sB[br][bcol]     = pb;
        __syncthreads();

        if (k0 + 32 < K) {
            Ap += 32; Bp += 32;
            pa0 = *(const uint4*)Ap;
            pa1 = *(const uint4*)(Ap + 8);
            pb  = *(const uint4*)Bp;
        }

        #pragma unroll
        for (int ks = 0; ks < 2; ks++) {
            const int kb = ks*8 + gk;
            uint32_t af[2][4];
            #pragma unroll
            for (int mi = 0; mi < 2; mi++) {
                int mr = wm + mi*16 + gr;
                af[mi][0] = sA[mr    ][kb];
                af[mi][1] = sA[mr + 8][kb];
                af[mi][2] = sA[mr    ][kb + 4];
                af[mi][3] = sA[mr + 8][kb + 4];
            }
            #pragma unroll
            for (int nj = 0; nj < 4; nj++) {
                int nc = wn + nj*8 + gr;
                uint32_t bf[2] = { sB[nc][kb], sB[nc][kb + 4] };
                #pragma unroll
                for (int mi = 0; mi < 2; mi++)
                    MMA_F16(acc[mi][nj], af[mi], bf);
            }
        }
        __syncthreads();
    }

    #pragma unroll
    for (int mi = 0; mi < 2; mi++) {
        #pragma unroll
        for (int nj = 0; nj < 4; nj++) {
            #pragma unroll
            for (int r = 0; r < 4; r++) {
                int row = m0 + wm + mi*16 + gr + ((r & 2) ? 8 : 0);
                int col = n0 + wn + nj*8 + 2*gk + (r & 1);
                int b = row >> 10, l = row & 1023;
                float v = acc[mi][nj][r] + (bias ? bias[col] : 0.f);
                if (MODE == 2) {
                    int mat = col / 384;
                    int cm  = col - mat * 384;
                    int h = cm / 48, d = cm % 48;
                    Out[(size_t)mat * (MM*CC)
                        + (size_t)(((b*8 + h) * 1024) + l) * 48 + d] = v;
                } else if (MODE == 3) {
                    v += aux[(size_t)(b*384 + col) * 1024 + l];
                    size_t idx = (size_t)row * 384 + col;
                    Out[idx] = v;
                    outH[idx] = __float2half(v);
                } else if (MODE == 1) {
                    v = 0.5f * v * (1.0f + erff(v * 0.70710678118654752f));
                    outH[(size_t)row * N + col] = __float2half(v);
                } else { // MODE 4
                    Out[(size_t)(b*384 + col) * 1024 + l] =
                        v + aux[(size_t)row * 384 + col];
                }
            }
        }
    }
}

// ============================================================
// FA2 fp16 warp-MMA attention (structure of the 289us kernel,
// single-precision fragments: 1 MMA per tile instead of 3)
// ============================================================
__global__ __launch_bounds__(256, 2)
void attn_mma(const float* __restrict__ q,
              const fp16* __restrict__ khg,
              const fp16* __restrict__ vhg,
              const float* __restrict__ rel_bias,
              fp16* __restrict__ attn_out)
{
    const int b  = blockIdx.y >> 3;
    const int h  = blockIdx.y & 7;
    const int bh = b*8 + h;
    const int q0 = blockIdx.x * 128;
    const int tid  = threadIdx.x;
    const int warp = tid >> 5, lane = tid & 31;
    const int gid  = lane >> 2;
    const int tig  = lane & 3;

    __shared__ uint32_t sK[64][28];   // [key][dpair]
    __shared__ uint32_t sV[48][36];   // [d][mpair]

    const float* qbase = q + (size_t)bh * LL * 48;
    const uint4* kh4 = (const uint4*)(khg + (size_t)bh * LL * 48);
    const fp16* vhb = vhg + (size_t)bh * 48 * 1024;
    const float* biasrow = rel_bias + (size_t)h * NBIAS_;

    const int qrow0 = q0 + warp*16 + gid;
    const int qrow1 = qrow0 + 8;
    const int ly0 = qrow0 >> 5, lx0 = qrow0 & 31;
    const int ly1 = qrow1 >> 5, lx1 = qrow1 & 31;

    // ---- Q fragments (fp16, converted once) ----
    uint32_t qf[3][4];
    #pragma unroll
    for (int kp = 0; kp < 3; kp++) {
        int d0 = 16*kp + 2*tig;
        #pragma unroll
        for (int rr = 0; rr < 2; rr++) {
            int row = rr ? qrow1 : qrow0;
            float2 e0 = *(const float2*)&qbase[(size_t)row*48 + d0];
            float2 e1 = *(const float2*)&qbase[(size_t)row*48 + d0 + 8];
            qf[kp][rr]   = packf(e0.x, e0.y);
            qf[kp][rr+2] = packf(e1.x, e1.y);
        }
    }

    float m0r = -1e30f, m1r = -1e30f, s0r = 0.f, s1r = 0.f;
    float o[6][4];
    #pragma unroll
    for (int nt = 0; nt < 6; nt++)
        #pragma unroll
        for (int r = 0; r < 4; r++) o[nt][r] = 0.f;

    for (int mc = 0; mc < LL; mc += 64) {
        __syncthreads();

        for (int e = tid; e < 384; e += 256) {
            int r = e / 6, j = e - r*6;
            *(uint4*)&sK[r][4*j] = kh4[(size_t)(mc + r)*6 + j];
        }
        for (int e = tid; e < 384; e += 256) {
            int d = e >> 3, j = e & 7;
            *(uint4*)&sV[d][4*j] = *((const uint4*)(vhb + (size_t)d*1024 + mc) + j);
        }
        __syncthreads();

        // ---- S = Q K^T ----
        float sc[8][4];
        #pragma unroll
        for (int t = 0; t < 8; t++)
            #pragma unroll
            for (int r = 0; r < 4; r++) sc[t][r] = 0.f;

        #pragma unroll
        for (int kp = 0; kp < 3; kp++) {
            #pragma unroll
            for (int t = 0; t < 8; t++) {
                int key = 8*t + gid;
                int dp  = 8*kp + tig;
                uint32_t bf[2] = { sK[key][dp], sK[key][dp + 4] };
                MMA_F16(sc[t], qf[kp], bf);
            }
        }

        // ---- bias + row max ----
        float rm0 = -1e30f, rm1 = -1e30f;
        #pragma unroll
        for (int t = 0; t < 8; t++) {
            int ma = mc + 8*t + 2*tig, mb = ma + 1;
            int may = ma >> 5, max_ = ma & 31;
            int mby = mb >> 5, mbx = mb & 31;
            sc[t][0] += biasrow[(may - ly0 + 32)*32 + (max_ - lx0 + 32)];
            sc[t][1] += biasrow[(mby - ly0 + 32)*32 + (mbx - lx0 + 32)];
            sc[t][2] += biasrow[(may - ly1 + 32)*32 + (max_ - lx1 + 32)];
            sc[t][3] += biasrow[(mby - ly1 + 32)*32 + (mbx - lx1 + 32)];
            rm0 = fmaxf(rm0, fmaxf(sc[t][0], sc[t][1]));
            rm1 = fmaxf(rm1, fmaxf(sc[t][2], sc[t][3]));
        }
        rm0 = fmaxf(rm0, __shfl_xor_sync(0xffffffffu, rm0, 1));
        rm0 = fmaxf(rm0, __shfl_xor_sync(0xffffffffu, rm0, 2));
        rm1 = fmaxf(rm1, __shfl_xor_sync(0xffffffffu, rm1, 1));
        rm1 = fmaxf(rm1, __shfl_xor_sync(0xffffffffu, rm1, 2));

        float nm0 = fmaxf(m0r, rm0), nm1 = fmaxf(m1r, rm1);
        float al0 = __expf(m0r - nm0), al1 = __expf(m1r - nm1);
        m0r = nm0; m1r = nm1;

        #pragma unroll
        for (int nt = 0; nt < 6; nt++) {
            o[nt][0] *= al0; o[nt][1] *= al0;
            o[nt][2] *= al1; o[nt][3] *= al1;
        }

        // ---- fused exp/pack + PV ----
        float ps0 = 0.f, ps1 = 0.f;
        #pragma unroll
        for (int kp = 0; kp < 4; kp++) {
            uint32_t pf[4];
            #pragma unroll
            for (int tt = 0; tt < 2; tt++) {
                int t = 2*kp + tt;
                float p0 = __expf(sc[t][0] - nm0);
                float p1 = __expf(sc[t][1] - nm0);
                float p2 = __expf(sc[t][2] - nm1);
                float p3 = __expf(sc[t][3] - nm1);
                ps0 += p0 + p1; ps1 += p2 + p3;
                pf[2*tt]   = packf(p0, p1);
                pf[2*tt+1] = packf(p2, p3);
            }
            #pragma unroll
            for (int nt = 0; nt < 6; nt++) {
                int d  = 8*nt + gid;
                int mp = 8*kp + tig;
                uint32_t bf[2] = { sV[d][mp], sV[d][mp + 4] };
                MMA_F16(o[nt], pf, bf);
            }
        }
        ps0 += __shfl_xor_sync(0xffffffffu, ps0, 1);
        ps0 += __shfl_xor_sync(0xffffffffu, ps0, 2);
        ps1 += __shfl_xor_sync(0xffffffffu, ps1, 1);
        ps1 += __shfl_xor_sync(0xffffffffu, ps1, 2);
        s0r = s0r * al0 + ps0;
        s1r = s1r * al1 + ps1;
    }

    float inv0 = 1.0f / s0r, inv1 = 1.0f / s1r;
    uint32_t* out32 = (uint32_t*)attn_out;
    #pragma unroll
    for (int nt = 0; nt < 6; nt++) {
        int d = 8*nt + 2*tig;
        size_t i0 = ((size_t)(b*LL + qrow0) * 384 + h*48 + d) >> 1;
        size_t i1 = ((size_t)(b*LL + qrow1) * 384 + h*48 + d) >> 1;
        out32[i0] = packf(o[nt][0]*inv0, o[nt][1]*inv0);
        out32[i1] = packf(o[nt][2]*inv1, o[nt][3]*inv1);
    }
}

// ============================================================
// launch
// ============================================================
extern "C" void kernel_launch(void* const* d_in, const int* in_sizes, int n_in,
                              void* d_out, int out_size)
{
    (void)in_sizes; (void)n_in; (void)out_size;
    const float* x        = (const float*)d_in[0];
    const float* gamma    = (const float*)d_in[1];
    const float* beta     = (const float*)d_in[2];
    const float* Wq       = (const float*)d_in[3];
    const float* Wk       = (const float*)d_in[4];
    const float* Wv       = (const float*)d_in[5];
    const float* Wo       = (const float*)d_in[6];
    const float* bo       = (const float*)d_in[7];
    const float* rel_bias = (const float*)d_in[8];
    const float* fc1_w    = (const float*)d_in[9];
    const float* fc1_b    = (const float*)d_in[10];
    const float* fc2_w    = (const float*)d_in[11];
    const float* fc2_b    = (const float*)d_in[12];
    float* out = (float*)d_out;

    fp16 *tok, *attn, *ytokh, *u1, *w, *kh, *vh;
    float *qkv, *ytok;
    cudaGetSymbolAddress((void**)&tok,   g_tok);
    cudaGetSymbolAddress((void**)&qkv,   g_qkv);
    cudaGetSymbolAddress((void**)&kh,    g_kh);
    cudaGetSymbolAddress((void**)&vh,    g_vh);
    cudaGetSymbolAddress((void**)&attn,  g_attn);
    cudaGetSymbolAddress((void**)&ytok,  g_ytok);
    cudaGetSymbolAddress((void**)&ytokh, g_ytokh);
    cudaGetSymbolAddress((void**)&u1,    g_u1);
    cudaGetSymbolAddress((void**)&w,     g_w);

    float* q  = qkv;
    float* kf = qkv + (size_t)MM*CC;
    float* vf = qkv + 2*(size_t)MM*CC;

    const int M = MM;

    conv_all<<<(NW_TOTAL + 255)/256, 256>>>(Wq, Wk, Wv, Wo, fc1_w, fc2_w, w);

    ln_kernel<<<dim3(LL/32, BB), dim3(32, 8)>>>(x, gamma, beta, tok);

    gemm_f16<2><<<dim3(1152/64, M/128), 256>>>(tok, w+OFF_WQ, nullptr, qkv,
                                               M, 1152, 384, nullptr, nullptr);

    kv_prep<<<dim3(LL/64, BB*NHH), 256>>>(kf, vf, kh, vh);

    attn_mma<<<dim3(LL/128, BB*NHH), 256>>>(q, kh, vh, rel_bias, attn);

    gemm_f16<3><<<dim3(384/64,  M/128), 256>>>(attn, w+OFF_WO, bo, ytok,
                                               M, 384, 384, x, ytokh);
    gemm_f16<1><<<dim3(1536/64, M/128), 256>>>(ytokh, w+OFF_FC1, fc1_b, nullptr,
                                               M, 1536, 384, nullptr, u1);
    gemm_f16<4><<<dim3(384/64,  M/128), 256>>>(u1, w+OFF_FC2, fc2_b, out,
                                               M, 384, 1536, ytok, nullptr);
}

// round 12
// speedup vs baseline: 3.0280x; 1.0458x over previous
#include <cuda_runtime.h>
#include <cuda_fp16.h>
#include <math.h>
#include <stdint.h>

// ---- problem constants ----
#define BB   8
#define CC   384
#define LL   1024
#define MM   (BB*LL)
#define NHH  8
#define DKK  48
#define DVV  48
#define CFF_ 1536
#define NBIAS_ 3969
#define LN_EPS_ 1e-5f

typedef __half fp16;

// ---- scratch ----
__device__ __align__(16) fp16  g_tok [MM*CC];
__device__ __align__(16) float g_qkv[3*MM*CC];        // q|k|v fp32
__device__ __align__(16) fp16  g_kh[MM*CC];           // [bh][key][d]
__device__ __align__(16) fp16  g_vh[MM*CC];           // [bh][d][tok]
__device__ __align__(16) fp16  g_attn[MM*CC];
__device__ __align__(16) float g_ytok[MM*CC];
__device__ __align__(16) fp16  g_ytokh[MM*CC];
__device__ __align__(16) fp16  g_u1[MM*CFF_];

#define OFF_WQ  0
#define OFF_WO  442368
#define OFF_FC1 589824
#define OFF_FC2 1179648
#define NW_TOTAL 1769472
__device__ __align__(16) fp16 g_w[NW_TOTAL];

__device__ __forceinline__ uint32_t packh(fp16 a, fp16 b) {
    uint16_t ua = *(uint16_t*)&a, ub = *(uint16_t*)&b;
    return (uint32_t)ua | ((uint32_t)ub << 16);
}
__device__ __forceinline__ uint32_t packf(float a, float b) {
    return packh(__float2half(a), __float2half(b));
}
__device__ __forceinline__ uint32_t smem_u32(const void* p) {
    uint32_t a;
    asm("{ .reg .u64 t; cvta.to.shared.u64 t, %1; cvt.u32.u64 %0, t; }"
        : "=r"(a) : "l"(p));
    return a;
}
__device__ __forceinline__ void cp16(uint32_t saddr, const void* g) {
    asm volatile("cp.async.cg.shared.global [%0], [%1], 16;"
                 :: "r"(saddr), "l"(g) : "memory");
}
#define CP_COMMIT() asm volatile("cp.async.commit_group;" ::: "memory")
#define CP_WAIT1()  asm volatile("cp.async.wait_group 1;" ::: "memory")
#define CP_WAIT0()  asm volatile("cp.async.wait_group 0;" ::: "memory")

#define MMA_F16(c, a, b) \
    asm volatile("mma.sync.aligned.m16n8k16.row.col.f32.f16.f16.f32 " \
        "{%0,%1,%2,%3}, {%4,%5,%6,%7}, {%8,%9}, {%0,%1,%2,%3};" \
        : "+f"(c[0]), "+f"(c[1]), "+f"(c[2]), "+f"(c[3]) \
        : "r"(a[0]), "r"(a[1]), "r"(a[2]), "r"(a[3]), "r"(b[0]), "r"(b[1]))

// ============================================================
// Merged weight fp16 conversion
// ============================================================
__global__ void conv_all(const float* __restrict__ Wq, const float* __restrict__ Wk,
                         const float* __restrict__ Wv, const float* __restrict__ Wo,
                         const float* __restrict__ f1, const float* __restrict__ f2,
                         fp16* __restrict__ w)
{
    int i = blockIdx.x * 256 + threadIdx.x;
    if (i >= NW_TOTAL) return;
    const float* src; int off;
    if (i < OFF_WO) {
        int m = i / 147456; off = i - m * 147456;
        src = (m == 0) ? Wq : (m == 1) ? Wk : Wv;
    } else if (i < OFF_FC1) { src = Wo; off = i - OFF_WO; }
    else if (i < OFF_FC2)   { src = f1; off = i - OFF_FC1; }
    else                    { src = f2; off = i - OFF_FC2; }
    w[i] = __float2half(src[off]);
}

// ============================================================
// K/V prep (unchanged)
// ============================================================
__global__ void kv_prep(const float* __restrict__ kin, const float* __restrict__ vin,
                        fp16* __restrict__ kh, fp16* __restrict__ vh)
{
    const int bh = blockIdx.y;
    const int l0 = blockIdx.x * 64;
    const int tid = threadIdx.x;
    __shared__ float sv[48][65];

    const float* kb = kin + ((size_t)bh*1024 + l0)*48;
    const float* vb = vin + ((size_t)bh*1024 + l0)*48;
    uint32_t* kh32 = (uint32_t*)(kh + ((size_t)bh*1024 + l0)*48);

    for (int e = tid; e < 1536; e += 256) {
        float2 p = *(const float2*)&kb[2*e];
        kh32[e] = packf(p.x, p.y);
    }
    for (int e = tid; e < 3072; e += 256) {
        int l = e / 48, d = e % 48;
        sv[d][l] = vb[e];
    }
    __syncthreads();
    uint32_t* vh32 = (uint32_t*)vh;
    for (int e = tid; e < 1536; e += 256) {
        int d = e >> 5, lp = e & 31;
        size_t i32 = ((((size_t)bh*48 + d)*1024 + l0) >> 1) + lp;
        vh32[i32] = packf(sv[d][2*lp], sv[d][2*lp + 1]);
    }
}

// ============================================================
// LayerNorm -> fp16 tokens (unchanged)
// ============================================================
__global__ void ln_kernel(const float* __restrict__ x,
                          const float* __restrict__ gamma,
                          const float* __restrict__ beta,
                          fp16* __restrict__ tok)
{
    int b  = blockIdx.y;
    int l0 = blockIdx.x * 32;
    int lane = threadIdx.x;
    int cy   = threadIdx.y;

    __shared__ float redS [8][32];
    __shared__ float redS2[8][32];
    __shared__ float s_mu[32], s_inv[32];
    __shared__ float buf[64][33];

    float s = 0.f, s2 = 0.f;
    for (int c = cy; c < CC; c += 8) {
        float v = x[((size_t)b*CC + c)*LL + l0 + lane];
        s += v; s2 += v*v;
    }
    redS[cy][lane] = s; redS2[cy][lane] = s2;
    __syncthreads();
    if (cy == 0) {
        float ts = 0.f, ts2 = 0.f;
        #pragma unroll
        for (int i = 0; i < 8; i++) { ts += redS[i][lane]; ts2 += redS2[i][lane]; }
        float mu = ts * (1.0f/384.0f);
        float var = ts2 * (1.0f/384.0f) - mu*mu;
        s_mu[lane] = mu;
        s_inv[lane] = rsqrtf(var + LN_EPS_);
    }
    __syncthreads();

    int tid = cy*32 + lane;
    for (int c0 = 0; c0 < CC; c0 += 64) {
        for (int e = tid; e < 64*32; e += 256) {
            int c = e >> 5, t = e & 31;
            buf[c][t] = x[((size_t)b*CC + c0 + c)*LL + l0 + t];
        }
        __syncthreads();
        for (int e = tid; e < 64*32; e += 256) {
            int c = e & 63, t = e >> 6;
            float v = (buf[c][t] - s_mu[t]) * s_inv[t];
            v = v * gamma[c0 + c] + beta[c0 + c];
            tok[((size_t)b*LL + l0 + t)*CC + c0 + c] = __float2half(v);
        }
        __syncthreads();
    }
}

// ============================================================
// fp16 warp-MMA GEMM, double-buffered smem (1 sync / k-step).
// stage = 15360 B: sA 128x20 u32 | sB 64x20 u32. Dynamic smem 30720 B.
// ============================================================
template<int MODE>
__global__ __launch_bounds__(256)
void gemm_f16(const fp16* __restrict__ A,
              const fp16* __restrict__ W,
              const float* __restrict__ bias,
              float* __restrict__ Out,
              int M, int N, int K,
              const float* __restrict__ aux,
              fp16* __restrict__ outH)
{
    extern __shared__ __align__(16) uint32_t dsm[];

    const int tid  = threadIdx.x;
    const int m0   = blockIdx.y * 128;
    const int n0   = blockIdx.x * 64;
    const int warp = tid >> 5, lane = tid & 31;
    const int wm   = (warp >> 1) * 32;
    const int wn   = (warp & 1) * 32;
    const int gk   = lane & 3;
    const int gr   = lane >> 2;

    const int ar = tid >> 1, ak = (tid & 1) * 16;
    const int br = tid >> 2, bk = (tid & 3) * 8;

    const fp16* Ap = A + (size_t)(m0 + ar) * K + ak;
    const fp16* Bp = W + (size_t)(n0 + br) * K + bk;

    uint4 pa0 = *(const uint4*)Ap;
    uint4 pa1 = *(const uint4*)(Ap + 8);
    uint4 pb  = *(const uint4*)Bp;

    float acc[2][4][4];
    #pragma unroll
    for (int mi = 0; mi < 2; mi++)
        #pragma unroll
        for (int nj = 0; nj < 4; nj++)
            #pragma unroll
            for (int r = 0; r < 4; r++) acc[mi][nj][r] = 0.f;

    const int acol = (tid & 1) * 8;
    const int bcol = (tid & 3) * 4;

    // prologue: STS stage 0
    {
        uint32_t* sA = dsm;
        uint32_t* sB = dsm + 2560;
        *(uint4*)&sA[ar*20 + acol]     = pa0;
        *(uint4*)&sA[ar*20 + acol + 4] = pa1;
        *(uint4*)&sB[br*20 + bcol]     = pb;
    }
    __syncthreads();

    int stage = 0;
    for (int k0 = 0; k0 < K; k0 += 32) {
        const bool more = (k0 + 32 < K);
        if (more) {
            Ap += 32; Bp += 32;
            pa0 = *(const uint4*)Ap;
            pa1 = *(const uint4*)(Ap + 8);
            pb  = *(const uint4*)Bp;
        }

        const uint32_t* sA = dsm + stage*3840;
        const uint32_t* sB = sA + 2560;

        #pragma unroll
        for (int ks = 0; ks < 2; ks++) {
            const int kb = ks*8 + gk;
            uint32_t af[2][4];
            #pragma unroll
            for (int mi = 0; mi < 2; mi++) {
                int mr = wm + mi*16 + gr;
                af[mi][0] = sA[(mr    )*20 + kb];
                af[mi][1] = sA[(mr + 8)*20 + kb];
                af[mi][2] = sA[(mr    )*20 + kb + 4];
                af[mi][3] = sA[(mr + 8)*20 + kb + 4];
            }
            #pragma unroll
            for (int nj = 0; nj < 4; nj++) {
                int nc = wn + nj*8 + gr;
                uint32_t bf[2] = { sB[nc*20 + kb], sB[nc*20 + kb + 4] };
                #pragma unroll
                for (int mi = 0; mi < 2; mi++)
                    MMA_F16(acc[mi][nj], af[mi], bf);
            }
        }

        if (more) {
            uint32_t* nA = dsm + (stage^1)*3840;
            uint32_t* nB = nA + 2560;
            *(uint4*)&nA[ar*20 + acol]     = pa0;
            *(uint4*)&nA[ar*20 + acol + 4] = pa1;
            *(uint4*)&nB[br*20 + bcol]     = pb;
            stage ^= 1;
            __syncthreads();
        }
    }

    #pragma unroll
    for (int mi = 0; mi < 2; mi++) {
        #pragma unroll
        for (int nj = 0; nj < 4; nj++) {
            #pragma unroll
            for (int r = 0; r < 4; r++) {
                int row = m0 + wm + mi*16 + gr + ((r & 2) ? 8 : 0);
                int col = n0 + wn + nj*8 + 2*gk + (r & 1);
                int b = row >> 10, l = row & 1023;
                float v = acc[mi][nj][r] + (bias ? bias[col] : 0.f);
                if (MODE == 2) {
                    int mat = col / 384;
                    int cm  = col - mat * 384;
                    int h = cm / 48, d = cm % 48;
                    Out[(size_t)mat * (MM*CC)
                        + (size_t)(((b*8 + h) * 1024) + l) * 48 + d] = v;
                } else if (MODE == 3) {
                    v += aux[(size_t)(b*384 + col) * 1024 + l];
                    size_t idx = (size_t)row * 384 + col;
                    Out[idx] = v;
                    outH[idx] = __float2half(v);
                } else if (MODE == 1) {
                    v = 0.5f * v * (1.0f + erff(v * 0.70710678118654752f));
                    outH[(size_t)row * N + col] = __float2half(v);
                } else { // MODE 4
                    Out[(size_t)(b*384 + col) * 1024 + l] =
                        v + aux[(size_t)row * 384 + col];
                }
            }
        }
    }
}

// ============================================================
// FA2 fp16 attention with cp.async double-buffered K/V staging.
// Dynamic smem: 2 stages x (sK 64x28 u32 + sV 48x36 u32) = 28160 B.
// ============================================================
#define AT_STAGE_U32 3520          // (64*28 + 48*36)
#define AT_K_OFF     0
#define AT_V_OFF     1792          // 64*28

__global__ __launch_bounds__(256, 2)
void attn_mma(const float* __restrict__ q,
              const fp16* __restrict__ khg,
              const fp16* __restrict__ vhg,
              const float* __restrict__ rel_bias,
              fp16* __restrict__ attn_out)
{
    extern __shared__ __align__(16) uint32_t asm_[];

    const int b  = blockIdx.y >> 3;
    const int h  = blockIdx.y & 7;
    const int bh = b*8 + h;
    const int q0 = blockIdx.x * 128;
    const int tid  = threadIdx.x;
    const int warp = tid >> 5, lane = tid & 31;
    const int gid  = lane >> 2;
    const int tig  = lane & 3;

    const float* qbase = q + (size_t)bh * LL * 48;
    const uint4* kh4 = (const uint4*)(khg + (size_t)bh * LL * 48);
    const fp16* vhb = vhg + (size_t)bh * 48 * 1024;
    const float* biasrow = rel_bias + (size_t)h * NBIAS_;

    const uint32_t sbase = smem_u32(asm_);

    const int qrow0 = q0 + warp*16 + gid;
    const int qrow1 = qrow0 + 8;
    const int ly0 = qrow0 >> 5, lx0 = qrow0 & 31;
    const int ly1 = qrow1 >> 5, lx1 = qrow1 & 31;

    // ---- Q fragments ----
    uint32_t qf[3][4];
    #pragma unroll
    for (int kp = 0; kp < 3; kp++) {
        int d0 = 16*kp + 2*tig;
        #pragma unroll
        for (int rr = 0; rr < 2; rr++) {
            int row = rr ? qrow1 : qrow0;
            float2 e0 = *(const float2*)&qbase[(size_t)row*48 + d0];
            float2 e1 = *(const float2*)&qbase[(size_t)row*48 + d0 + 8];
            qf[kp][rr]   = packf(e0.x, e0.y);
            qf[kp][rr+2] = packf(e1.x, e1.y);
        }
    }

    float m0r = -1e30f, m1r = -1e30f, s0r = 0.f, s1r = 0.f;
    float o[6][4];
    #pragma unroll
    for (int nt = 0; nt < 6; nt++)
        #pragma unroll
        for (int r = 0; r < 4; r++) o[nt][r] = 0.f;

    // staging issue: chunk mc into buffer buf
    auto issue = [&](int mc, int buf) {
        uint32_t kb = sbase + (buf*AT_STAGE_U32 + AT_K_OFF)*4;
        uint32_t vb = sbase + (buf*AT_STAGE_U32 + AT_V_OFF)*4;
        for (int e = tid; e < 384; e += 256) {
            int r = e / 6, j = e - r*6;
            cp16(kb + (r*28 + 4*j)*4, kh4 + (size_t)(mc + r)*6 + j);
        }
        for (int e = tid; e < 384; e += 256) {
            int d = e >> 3, j = e & 7;
            cp16(vb + (d*36 + 4*j)*4, (const uint4*)(vhb + (size_t)d*1024 + mc) + j);
        }
    };

    issue(0, 0);
    CP_COMMIT();

    for (int ic = 0; ic < 16; ic++) {
        const int mc = ic * 64;
        const int buf = ic & 1;

        if (ic + 1 < 16) {
            issue(mc + 64, buf ^ 1);
            CP_COMMIT();
            CP_WAIT1();
        } else {
            CP_WAIT0();
        }
        __syncthreads();

        const uint32_t* sK = asm_ + buf*AT_STAGE_U32 + AT_K_OFF;
        const uint32_t* sV = asm_ + buf*AT_STAGE_U32 + AT_V_OFF;

        // ---- S = Q K^T ----
        float sc[8][4];
        #pragma unroll
        for (int t = 0; t < 8; t++)
            #pragma unroll
            for (int r = 0; r < 4; r++) sc[t][r] = 0.f;

        #pragma unroll
        for (int kp = 0; kp < 3; kp++) {
            #pragma unroll
            for (int t = 0; t < 8; t++) {
                int key = 8*t + gid;
                int dp  = 8*kp + tig;
                uint32_t bf[2] = { sK[key*28 + dp], sK[key*28 + dp + 4] };
                MMA_F16(sc[t], qf[kp], bf);
            }
        }

        // ---- bias + row max ----
        float rm0 = -1e30f, rm1 = -1e30f;
        #pragma unroll
        for (int t = 0; t < 8; t++) {
            int ma = mc + 8*t + 2*tig, mb = ma + 1;
            int may = ma >> 5, max_ = ma & 31;
            int mby = mb >> 5, mbx = mb & 31;
            sc[t][0] += biasrow[(may - ly0 + 32)*32 + (max_ - lx0 + 32)];
            sc[t][1] += biasrow[(mby - ly0 + 32)*32 + (mbx - lx0 + 32)];
            sc[t][2] += biasrow[(may - ly1 + 32)*32 + (max_ - lx1 + 32)];
            sc[t][3] += biasrow[(mby - ly1 + 32)*32 + (mbx - lx1 + 32)];
            rm0 = fmaxf(rm0, fmaxf(sc[t][0], sc[t][1]));
            rm1 = fmaxf(rm1, fmaxf(sc[t][2], sc[t][3]));
        }
        rm0 = fmaxf(rm0, __shfl_xor_sync(0xffffffffu, rm0, 1));
        rm0 = fmaxf(rm0, __shfl_xor_sync(0xffffffffu, rm0, 2));
        rm1 = fmaxf(rm1, __shfl_xor_sync(0xffffffffu, rm1, 1));
        rm1 = fmaxf(rm1, __shfl_xor_sync(0xffffffffu, rm1, 2));

        float nm0 = fmaxf(m0r, rm0), nm1 = fmaxf(m1r, rm1);
        float al0 = __expf(m0r - nm0), al1 = __expf(m1r - nm1);
        m0r = nm0; m1r = nm1;

        #pragma unroll
        for (int nt = 0; nt < 6; nt++) {
            o[nt][0] *= al0; o[nt][1] *= al0;
            o[nt][2] *= al1; o[nt][3] *= al1;
        }

        // ---- fused exp/pack + PV ----
        float ps0 = 0.f, ps1 = 0.f;
        #pragma unroll
        for (int kp = 0; kp < 4; kp++) {
            uint32_t pf[4];
            #pragma unroll
            for (int tt = 0; tt < 2; tt++) {
                int t = 2*kp + tt;
                float p0 = __expf(sc[t][0] - nm0);
                float p1 = __expf(sc[t][1] - nm0);
                float p2 = __expf(sc[t][2] - nm1);
                float p3 = __expf(sc[t][3] - nm1);
                ps0 += p0 + p1; ps1 += p2 + p3;
                pf[2*tt]   = packf(p0, p1);
                pf[2*tt+1] = packf(p2, p3);
            }
            #pragma unroll
            for (int nt = 0; nt < 6; nt++) {
                int d  = 8*nt + gid;
                int mp = 8*kp + tig;
                uint32_t bf[2] = { sV[d*36 + mp], sV[d*36 + mp + 4] };
                MMA_F16(o[nt], pf, bf);
            }
        }
        ps0 += __shfl_xor_sync(0xffffffffu, ps0, 1);
        ps0 += __shfl_xor_sync(0xffffffffu, ps0, 2);
        ps1 += __shfl_xor_sync(0xffffffffu, ps1, 1);
        ps1 += __shfl_xor_sync(0xffffffffu, ps1, 2);
        s0r = s0r * al0 + ps0;
        s1r = s1r * al1 + ps1;

        __syncthreads();   // staging of next-next chunk must not overwrite live buf
    }

    float inv0 = 1.0f / s0r, inv1 = 1.0f / s1r;
    uint32_t* out32 = (uint32_t*)attn_out;
    #pragma unroll
    for (int nt = 0; nt < 6; nt++) {
        int d = 8*nt + 2*tig;
        size_t i0 = ((size_t)(b*LL + qrow0) * 384 + h*48 + d) >> 1;
        size_t i1 = ((size_t)(b*LL + qrow1) * 384 + h*48 + d) >> 1;
        out32[i0] = packf(o[nt][0]*inv0, o[nt][1]*inv0);
        out32[i1] = packf(o[nt][2]*inv1, o[nt][3]*inv1);
    }
}

// ============================================================
// launch
// ============================================================
extern "C" void kernel_launch(void* const* d_in, const int* in_sizes, int n_in,
                              void* d_out, int out_size)
{
    (void)in_sizes; (void)n_in; (void)out_size;
    const float* x        = (const float*)d_in[0];
    const float* gamma    = (const float*)d_in[1];
    const float* beta     = (const float*)d_in[2];
    const float* Wq       = (const float*)d_in[3];
    const float* Wk       = (const float*)d_in[4];
    const float* Wv       = (const float*)d_in[5];
    const float* Wo       = (const float*)d_in[6];
    const float* bo       = (const float*)d_in[7];
    const float* rel_bias = (const float*)d_in[8];
    const float* fc1_w    = (const float*)d_in[9];
    const float* fc1_b    = (const float*)d_in[10];
    const float* fc2_w    = (const float*)d_in[11];
    const float* fc2_b    = (const float*)d_in[12];
    float* out = (float*)d_out;

    fp16 *tok, *attn, *ytokh, *u1, *w, *kh, *vh;
    float *qkv, *ytok;
    cudaGetSymbolAddress((void**)&tok,   g_tok);
    cudaGetSymbolAddress((void**)&qkv,   g_qkv);
    cudaGetSymbolAddress((void**)&kh,    g_kh);
    cudaGetSymbolAddress((void**)&vh,    g_vh);
    cudaGetSymbolAddress((void**)&attn,  g_attn);
    cudaGetSymbolAddress((void**)&ytok,  g_ytok);
    cudaGetSymbolAddress((void**)&ytokh, g_ytokh);
    cudaGetSymbolAddress((void**)&u1,    g_u1);
    cudaGetSymbolAddress((void**)&w,     g_w);

    float* q  = qkv;
    float* kf = qkv + (size_t)MM*CC;
    float* vf = qkv + 2*(size_t)MM*CC;

    const int M = MM;
    const int GEMM_SMEM = 30720;   // 2 stages x 15360 B
    const int ATTN_SMEM = 28160;   // 2 stages x 14080 B

    conv_all<<<(NW_TOTAL + 255)/256, 256>>>(Wq, Wk, Wv, Wo, fc1_w, fc2_w, w);

    ln_kernel<<<dim3(LL/32, BB), dim3(32, 8)>>>(x, gamma, beta, tok);

    gemm_f16<2><<<dim3(1152/64, M/128), 256, GEMM_SMEM>>>(tok, w+OFF_WQ, nullptr, qkv,
                                               M, 1152, 384, nullptr, nullptr);

    kv_prep<<<dim3(LL/64, BB*NHH), 256>>>(kf, vf, kh, vh);

    attn_mma<<<dim3(LL/128, BB*NHH), 256, ATTN_SMEM>>>(q, kh, vh, rel_bias, attn);

    gemm_f16<3><<<dim3(384/64,  M/128), 256, GEMM_SMEM>>>(attn, w+OFF_WO, bo, ytok,
                                               M, 384, 384, x, ytokh);
    gemm_f16<1><<<dim3(1536/64, M/128), 256, GEMM_SMEM>>>(ytokh, w+OFF_FC1, fc1_b, nullptr,
                                               M, 1536, 384, nullptr, u1);
    gemm_f16<4><<<dim3(384/64,  M/128), 256, GEMM_SMEM>>>(u1, w+OFF_FC2, fc2_b, out,
                                               M, 384, 1536, ytok, nullptr);
}

// round 13
// speedup vs baseline: 3.0801x; 1.0172x over previous
#include <cuda_runtime.h>
#include <cuda_fp16.h>
#include <math.h>
#include <stdint.h>

// ---- problem constants ----
#define BB   8
#define CC   384
#define LL   1024
#define MM   (BB*LL)
#define NHH  8
#define DKK  48
#define DVV  48
#define CFF_ 1536
#define NBIAS_ 3969
#define LN_EPS_ 1e-5f

typedef __half fp16;

// ---- scratch ----
__device__ __align__(16) fp16  g_tok [MM*CC];
__device__ __align__(16) float g_qkv[3*MM*CC];        // q|k|v fp32
__device__ __align__(16) fp16  g_kh[MM*CC];           // [bh][key][d]
__device__ __align__(16) fp16  g_vh[MM*CC];           // [bh][d][tok]
__device__ __align__(16) fp16  g_attn[MM*CC];
__device__ __align__(16) float g_ytok[MM*CC];
__device__ __align__(16) fp16  g_ytokh[MM*CC];
__device__ __align__(16) fp16  g_u1[MM*CFF_];

#define OFF_WQ  0
#define OFF_WO  442368
#define OFF_FC1 589824
#define OFF_FC2 1179648
#define NW_TOTAL 1769472
__device__ __align__(16) fp16 g_w[NW_TOTAL];

__device__ __forceinline__ uint32_t packh(fp16 a, fp16 b) {
    uint16_t ua = *(uint16_t*)&a, ub = *(uint16_t*)&b;
    return (uint32_t)ua | ((uint32_t)ub << 16);
}
__device__ __forceinline__ uint32_t packf(float a, float b) {
    return packh(__float2half(a), __float2half(b));
}
__device__ __forceinline__ uint32_t smem_u32(const void* p) {
    uint32_t a;
    asm("{ .reg .u64 t; cvta.to.shared.u64 t, %1; cvt.u32.u64 %0, t; }"
        : "=r"(a) : "l"(p));
    return a;
}
__device__ __forceinline__ void cp16(uint32_t saddr, const void* g) {
    asm volatile("cp.async.cg.shared.global [%0], [%1], 16;"
                 :: "r"(saddr), "l"(g) : "memory");
}
#define CP_COMMIT() asm volatile("cp.async.commit_group;" ::: "memory")
#define CP_WAIT1()  asm volatile("cp.async.wait_group 1;" ::: "memory")
#define CP_WAIT0()  asm volatile("cp.async.wait_group 0;" ::: "memory")

#define MMA_F16(c, a, b) \
    asm volatile("mma.sync.aligned.m16n8k16.row.col.f32.f16.f16.f32 " \
        "{%0,%1,%2,%3}, {%4,%5,%6,%7}, {%8,%9}, {%0,%1,%2,%3};" \
        : "+f"(c[0]), "+f"(c[1]), "+f"(c[2]), "+f"(c[3]) \
        : "r"(a[0]), "r"(a[1]), "r"(a[2]), "r"(a[3]), "r"(b[0]), "r"(b[1]))

// ============================================================
// Merged weight fp16 conversion
// ============================================================
__global__ void conv_all(const float* __restrict__ Wq, const float* __restrict__ Wk,
                         const float* __restrict__ Wv, const float* __restrict__ Wo,
                         const float* __restrict__ f1, const float* __restrict__ f2,
                         fp16* __restrict__ w)
{
    int i = blockIdx.x * 256 + threadIdx.x;
    if (i >= NW_TOTAL) return;
    const float* src; int off;
    if (i < OFF_WO) {
        int m = i / 147456; off = i - m * 147456;
        src = (m == 0) ? Wq : (m == 1) ? Wk : Wv;
    } else if (i < OFF_FC1) { src = Wo; off = i - OFF_WO; }
    else if (i < OFF_FC2)   { src = f1; off = i - OFF_FC1; }
    else                    { src = f2; off = i - OFF_FC2; }
    w[i] = __float2half(src[off]);
}

// ============================================================
// K/V prep (unchanged)
// ============================================================
__global__ void kv_prep(const float* __restrict__ kin, const float* __restrict__ vin,
                        fp16* __restrict__ kh, fp16* __restrict__ vh)
{
    const int bh = blockIdx.y;
    const int l0 = blockIdx.x * 64;
    const int tid = threadIdx.x;
    __shared__ float sv[48][65];

    const float* kb = kin + ((size_t)bh*1024 + l0)*48;
    const float* vb = vin + ((size_t)bh*1024 + l0)*48;
    uint32_t* kh32 = (uint32_t*)(kh + ((size_t)bh*1024 + l0)*48);

    for (int e = tid; e < 1536; e += 256) {
        float2 p = *(const float2*)&kb[2*e];
        kh32[e] = packf(p.x, p.y);
    }
    for (int e = tid; e < 3072; e += 256) {
        int l = e / 48, d = e % 48;
        sv[d][l] = vb[e];
    }
    __syncthreads();
    uint32_t* vh32 = (uint32_t*)vh;
    for (int e = tid; e < 1536; e += 256) {
        int d = e >> 5, lp = e & 31;
        size_t i32 = ((((size_t)bh*48 + d)*1024 + l0) >> 1) + lp;
        vh32[i32] = packf(sv[d][2*lp], sv[d][2*lp + 1]);
    }
}

// ============================================================
// LayerNorm v2: single global read via smem tile (50688 B dynamic).
// grid (L/32, B), block 256.
// ============================================================
__global__ void ln_kernel(const float* __restrict__ x,
                          const float* __restrict__ gamma,
                          const float* __restrict__ beta,
                          fp16* __restrict__ tok)
{
    extern __shared__ __align__(16) float sbuf[];   // [384][33]
    __shared__ float redS [8][32];
    __shared__ float redS2[8][32];
    __shared__ float s_mu[32], s_inv[32];

    const int b  = blockIdx.y;
    const int l0 = blockIdx.x * 32;
    const int tid = threadIdx.x;
    const int lane = tid & 31;
    const int cy   = tid >> 5;

    // pass A: load x once, coalesced along tokens
    for (int e = tid; e < CC*32; e += 256) {
        int c = e >> 5, t = e & 31;
        sbuf[c*33 + t] = x[((size_t)b*CC + c)*LL + l0 + t];
    }
    __syncthreads();

    // stats (same summation order as before)
    float s = 0.f, s2 = 0.f;
    for (int c = cy; c < CC; c += 8) {
        float v = sbuf[c*33 + lane];
        s += v; s2 += v*v;
    }
    redS[cy][lane] = s; redS2[cy][lane] = s2;
    __syncthreads();
    if (cy == 0) {
        float ts = 0.f, ts2 = 0.f;
        #pragma unroll
        for (int i = 0; i < 8; i++) { ts += redS[i][lane]; ts2 += redS2[i][lane]; }
        float mu = ts * (1.0f/384.0f);
        float var = ts2 * (1.0f/384.0f) - mu*mu;
        s_mu[lane] = mu;
        s_inv[lane] = rsqrtf(var + LN_EPS_);
    }
    __syncthreads();

    // pass B: write fp16 token-major, coalesced along channels
    for (int e = tid; e < CC*32; e += 256) {
        int t = e / CC, c = e - t*CC;
        float v = (sbuf[c*33 + t] - s_mu[t]) * s_inv[t];
        v = v * gamma[c] + beta[c];
        tok[((size_t)b*LL + l0 + t)*CC + c] = __float2half(v);
    }
}

// ============================================================
// fp16 warp-MMA GEMM, double-buffered smem (unchanged from r12)
// ============================================================
template<int MODE>
__global__ __launch_bounds__(256)
void gemm_f16(const fp16* __restrict__ A,
              const fp16* __restrict__ W,
              const float* __restrict__ bias,
              float* __restrict__ Out,
              int M, int N, int K,
              const float* __restrict__ aux,
              fp16* __restrict__ outH)
{
    extern __shared__ __align__(16) uint32_t dsm[];

    const int tid  = threadIdx.x;
    const int m0   = blockIdx.y * 128;
    const int n0   = blockIdx.x * 64;
    const int warp = tid >> 5, lane = tid & 31;
    const int wm   = (warp >> 1) * 32;
    const int wn   = (warp & 1) * 32;
    const int gk   = lane & 3;
    const int gr   = lane >> 2;

    const int ar = tid >> 1, ak = (tid & 1) * 16;
    const int br = tid >> 2, bk = (tid & 3) * 8;

    const fp16* Ap = A + (size_t)(m0 + ar) * K + ak;
    const fp16* Bp = W + (size_t)(n0 + br) * K + bk;

    uint4 pa0 = *(const uint4*)Ap;
    uint4 pa1 = *(const uint4*)(Ap + 8);
    uint4 pb  = *(const uint4*)Bp;

    float acc[2][4][4];
    #pragma unroll
    for (int mi = 0; mi < 2; mi++)
        #pragma unroll
        for (int nj = 0; nj < 4; nj++)
            #pragma unroll
            for (int r = 0; r < 4; r++) acc[mi][nj][r] = 0.f;

    const int acol = (tid & 1) * 8;
    const int bcol = (tid & 3) * 4;

    {
        uint32_t* sA = dsm;
        uint32_t* sB = dsm + 2560;
        *(uint4*)&sA[ar*20 + acol]     = pa0;
        *(uint4*)&sA[ar*20 + acol + 4] = pa1;
        *(uint4*)&sB[br*20 + bcol]     = pb;
    }
    __syncthreads();

    int stage = 0;
    for (int k0 = 0; k0 < K; k0 += 32) {
        const bool more = (k0 + 32 < K);
        if (more) {
            Ap += 32; Bp += 32;
            pa0 = *(const uint4*)Ap;
            pa1 = *(const uint4*)(Ap + 8);
            pb  = *(const uint4*)Bp;
        }

        const uint32_t* sA = dsm + stage*3840;
        const uint32_t* sB = sA + 2560;

        #pragma unroll
        for (int ks = 0; ks < 2; ks++) {
            const int kb = ks*8 + gk;
            uint32_t af[2][4];
            #pragma unroll
            for (int mi = 0; mi < 2; mi++) {
                int mr = wm + mi*16 + gr;
                af[mi][0] = sA[(mr    )*20 + kb];
                af[mi][1] = sA[(mr + 8)*20 + kb];
                af[mi][2] = sA[(mr    )*20 + kb + 4];
                af[mi][3] = sA[(mr + 8)*20 + kb + 4];
            }
            #pragma unroll
            for (int nj = 0; nj < 4; nj++) {
                int nc = wn + nj*8 + gr;
                uint32_t bf[2] = { sB[nc*20 + kb], sB[nc*20 + kb + 4] };
                #pragma unroll
                for (int mi = 0; mi < 2; mi++)
                    MMA_F16(acc[mi][nj], af[mi], bf);
            }
        }

        if (more) {
            uint32_t* nA = dsm + (stage^1)*3840;
            uint32_t* nB = nA + 2560;
            *(uint4*)&nA[ar*20 + acol]     = pa0;
            *(uint4*)&nA[ar*20 + acol + 4] = pa1;
            *(uint4*)&nB[br*20 + bcol]     = pb;
            stage ^= 1;
            __syncthreads();
        }
    }

    #pragma unroll
    for (int mi = 0; mi < 2; mi++) {
        #pragma unroll
        for (int nj = 0; nj < 4; nj++) {
            #pragma unroll
            for (int r = 0; r < 4; r++) {
                int row = m0 + wm + mi*16 + gr + ((r & 2) ? 8 : 0);
                int col = n0 + wn + nj*8 + 2*gk + (r & 1);
                int b = row >> 10, l = row & 1023;
                float v = acc[mi][nj][r] + (bias ? bias[col] : 0.f);
                if (MODE == 2) {
                    int mat = col / 384;
                    int cm  = col - mat * 384;
                    int h = cm / 48, d = cm % 48;
                    Out[(size_t)mat * (MM*CC)
                        + (size_t)(((b*8 + h) * 1024) + l) * 48 + d] = v;
                } else if (MODE == 3) {
                    v += aux[(size_t)(b*384 + col) * 1024 + l];
                    size_t idx = (size_t)row * 384 + col;
                    Out[idx] = v;
                    outH[idx] = __float2half(v);
                } else if (MODE == 1) {
                    v = 0.5f * v * (1.0f + erff(v * 0.70710678118654752f));
                    outH[(size_t)row * N + col] = __float2half(v);
                } else { // MODE 4
                    Out[(size_t)(b*384 + col) * 1024 + l] =
                        v + aux[(size_t)row * 384 + col];
                }
            }
        }
    }
}

// ============================================================
// FA2 fp16 attention: cp.async double-buffered K/V + bias in smem.
// ============================================================
#define AT_STAGE_U32 3520
#define AT_K_OFF     0
#define AT_V_OFF     1792

__global__ __launch_bounds__(256, 2)
void attn_mma(const float* __restrict__ q,
              const fp16* __restrict__ khg,
              const fp16* __restrict__ vhg,
              const float* __restrict__ rel_bias,
              fp16* __restrict__ attn_out)
{
    extern __shared__ __align__(16) uint32_t asm_[];
    __shared__ float sBias[NBIAS_];

    const int b  = blockIdx.y >> 3;
    const int h  = blockIdx.y & 7;
    const int bh = b*8 + h;
    const int q0 = blockIdx.x * 128;
    const int tid  = threadIdx.x;
    const int warp = tid >> 5, lane = tid & 31;
    const int gid  = lane >> 2;
    const int tig  = lane & 3;

    const float* qbase = q + (size_t)bh * LL * 48;
    const uint4* kh4 = (const uint4*)(khg + (size_t)bh * LL * 48);
    const fp16* vhb = vhg + (size_t)bh * 48 * 1024;
    const float* biasrow = rel_bias + (size_t)h * NBIAS_;

    const uint32_t sbase = smem_u32(asm_);

    // cache the bias table (visible after the first in-loop __syncthreads)
    for (int e = tid; e < NBIAS_; e += 256) sBias[e] = biasrow[e];

    const int qrow0 = q0 + warp*16 + gid;
    const int qrow1 = qrow0 + 8;
    const int ly0 = qrow0 >> 5, lx0 = qrow0 & 31;
    const int ly1 = qrow1 >> 5, lx1 = qrow1 & 31;

    uint32_t qf[3][4];
    #pragma unroll
    for (int kp = 0; kp < 3; kp++) {
        int d0 = 16*kp + 2*tig;
        #pragma unroll
        for (int rr = 0; rr < 2; rr++) {
            int row = rr ? qrow1 : qrow0;
            float2 e0 = *(const float2*)&qbase[(size_t)row*48 + d0];
            float2 e1 = *(const float2*)&qbase[(size_t)row*48 + d0 + 8];
            qf[kp][rr]   = packf(e0.x, e0.y);
            qf[kp][rr+2] = packf(e1.x, e1.y);
        }
    }

    float m0r = -1e30f, m1r = -1e30f, s0r = 0.f, s1r = 0.f;
    float o[6][4];
    #pragma unroll
    for (int nt = 0; nt < 6; nt++)
        #pragma unroll
        for (int r = 0; r < 4; r++) o[nt][r] = 0.f;

    auto issue = [&](int mc, int buf) {
        uint32_t kb = sbase + (buf*AT_STAGE_U32 + AT_K_OFF)*4;
        uint32_t vb = sbase + (buf*AT_STAGE_U32 + AT_V_OFF)*4;
        for (int e = tid; e < 384; e += 256) {
            int r = e / 6, j = e - r*6;
            cp16(kb + (r*28 + 4*j)*4, kh4 + (size_t)(mc + r)*6 + j);
        }
        for (int e = tid; e < 384; e += 256) {
            int d = e >> 3, j = e & 7;
            cp16(vb + (d*36 + 4*j)*4, (const uint4*)(vhb + (size_t)d*1024 + mc) + j);
        }
    };

    issue(0, 0);
    CP_COMMIT();

    for (int ic = 0; ic < 16; ic++) {
        const int mc = ic * 64;
        const int buf = ic & 1;

        if (ic + 1 < 16) {
            issue(mc + 64, buf ^ 1);
            CP_COMMIT();
            CP_WAIT1();
        } else {
            CP_WAIT0();
        }
        __syncthreads();

        const uint32_t* sK = asm_ + buf*AT_STAGE_U32 + AT_K_OFF;
        const uint32_t* sV = asm_ + buf*AT_STAGE_U32 + AT_V_OFF;

        float sc[8][4];
        #pragma unroll
        for (int t = 0; t < 8; t++)
            #pragma unroll
            for (int r = 0; r < 4; r++) sc[t][r] = 0.f;

        #pragma unroll
        for (int kp = 0; kp < 3; kp++) {
            #pragma unroll
            for (int t = 0; t < 8; t++) {
                int key = 8*t + gid;
                int dp  = 8*kp + tig;
                uint32_t bf[2] = { sK[key*28 + dp], sK[key*28 + dp + 4] };
                MMA_F16(sc[t], qf[kp], bf);
            }
        }

        float rm0 = -1e30f, rm1 = -1e30f;
        #pragma unroll
        for (int t = 0; t < 8; t++) {
            int ma = mc + 8*t + 2*tig, mb = ma + 1;
            int may = ma >> 5, max_ = ma & 31;
            int mby = mb >> 5, mbx = mb & 31;
            sc[t][0] += sBias[(may - ly0 + 32)*32 + (max_ - lx0 + 32)];
            sc[t][1] += sBias[(mby - ly0 + 32)*32 + (mbx - lx0 + 32)];
            sc[t][2] += sBias[(may - ly1 + 32)*32 + (max_ - lx1 + 32)];
            sc[t][3] += sBias[(mby - ly1 + 32)*32 + (mbx - lx1 + 32)];
            rm0 = fmaxf(rm0, fmaxf(sc[t][0], sc[t][1]));
            rm1 = fmaxf(rm1, fmaxf(sc[t][2], sc[t][3]));
        }
        rm0 = fmaxf(rm0, __shfl_xor_sync(0xffffffffu, rm0, 1));
        rm0 = fmaxf(rm0, __shfl_xor_sync(0xffffffffu, rm0, 2));
        rm1 = fmaxf(rm1, __shfl_xor_sync(0xffffffffu, rm1, 1));
        rm1 = fmaxf(rm1, __shfl_xor_sync(0xffffffffu, rm1, 2));

        float nm0 = fmaxf(m0r, rm0), nm1 = fmaxf(m1r, rm1);
        float al0 = __expf(m0r - nm0), al1 = __expf(m1r - nm1);
        m0r = nm0; m1r = nm1;

        #pragma unroll
        for (int nt = 0; nt < 6; nt++) {
            o[nt][0] *= al0; o[nt][1] *= al0;
            o[nt][2] *= al1; o[nt][3] *= al1;
        }

        float ps0 = 0.f, ps1 = 0.f;
        #pragma unroll
        for (int kp = 0; kp < 4; kp++) {
            uint32_t pf[4];
            #pragma unroll
            for (int tt = 0; tt < 2; tt++) {
                int t = 2*kp + tt;
                float p0 = __expf(sc[t][0] - nm0);
                float p1 = __expf(sc[t][1] - nm0);
                float p2 = __expf(sc[t][2] - nm1);
                float p3 = __expf(sc[t][3] - nm1);
                ps0 += p0 + p1; ps1 += p2 + p3;
                pf[2*tt]   = packf(p0, p1);
                pf[2*tt+1] = packf(p2, p3);
            }
            #pragma unroll
            for (int nt = 0; nt < 6; nt++) {
                int d  = 8*nt + gid;
                int mp = 8*kp + tig;
                uint32_t bf[2] = { sV[d*36 + mp], sV[d*36 + mp + 4] };
                MMA_F16(o[nt], pf, bf);
            }
        }
        ps0 += __shfl_xor_sync(0xffffffffu, ps0, 1);
        ps0 += __shfl_xor_sync(0xffffffffu, ps0, 2);
        ps1 += __shfl_xor_sync(0xffffffffu, ps1, 1);
        ps1 += __shfl_xor_sync(0xffffffffu, ps1, 2);
        s0r = s0r * al0 + ps0;
        s1r = s1r * al1 + ps1;

        __syncthreads();
    }

    float inv0 = 1.0f / s0r, inv1 = 1.0f / s1r;
    uint32_t* out32 = (uint32_t*)attn_out;
    #pragma unroll
    for (int nt = 0; nt < 6; nt++) {
        int d = 8*nt + 2*tig;
        size_t i0 = ((size_t)(b*LL + qrow0) * 384 + h*48 + d) >> 1;
        size_t i1 = ((size_t)(b*LL + qrow1) * 384 + h*48 + d) >> 1;
        out32[i0] = packf(o[nt][0]*inv0, o[nt][1]*inv0);
        out32[i1] = packf(o[nt][2]*inv1, o[nt][3]*inv1);
    }
}

// ============================================================
// launch
// ============================================================
extern "C" void kernel_launch(void* const* d_in, const int* in_sizes, int n_in,
                              void* d_out, int out_size)
{
    (void)in_sizes; (void)n_in; (void)out_size;
    const float* x        = (const float*)d_in[0];
    const float* gamma    = (const float*)d_in[1];
    const float* beta     = (const float*)d_in[2];
    const float* Wq       = (const float*)d_in[3];
    const float* Wk       = (const float*)d_in[4];
    const float* Wv       = (const float*)d_in[5];
    const float* Wo       = (const float*)d_in[6];
    const float* bo       = (const float*)d_in[7];
    const float* rel_bias = (const float*)d_in[8];
    const float* fc1_w    = (const float*)d_in[9];
    const float* fc1_b    = (const float*)d_in[10];
    const float* fc2_w    = (const float*)d_in[11];
    const float* fc2_b    = (const float*)d_in[12];
    float* out = (float*)d_out;

    fp16 *tok, *attn, *ytokh, *u1, *w, *kh, *vh;
    float *qkv, *ytok;
    cudaGetSymbolAddress((void**)&tok,   g_tok);
    cudaGetSymbolAddress((void**)&qkv,   g_qkv);
    cudaGetSymbolAddress((void**)&kh,    g_kh);
    cudaGetSymbolAddress((void**)&vh,    g_vh);
    cudaGetSymbolAddress((void**)&attn,  g_attn);
    cudaGetSymbolAddress((void**)&ytok,  g_ytok);
    cudaGetSymbolAddress((void**)&ytokh, g_ytokh);
    cudaGetSymbolAddress((void**)&u1,    g_u1);
    cudaGetSymbolAddress((void**)&w,     g_w);

    float* q  = qkv;
    float* kf = qkv + (size_t)MM*CC;
    float* vf = qkv + 2*(size_t)MM*CC;

    const int M = MM;
    const int GEMM_SMEM = 30720;
    const int ATTN_SMEM = 28160;
    const int LN_SMEM   = 384*33*4;   // 50688 > default 48K -> needs attribute

    cudaFuncSetAttribute(ln_kernel, cudaFuncAttributeMaxDynamicSharedMemorySize, LN_SMEM);

    conv_all<<<(NW_TOTAL + 255)/256, 256>>>(Wq, Wk, Wv, Wo, fc1_w, fc2_w, w);

    ln_kernel<<<dim3(LL/32, BB), 256, LN_SMEM>>>(x, gamma, beta, tok);

    gemm_f16<2><<<dim3(1152/64, M/128), 256, GEMM_SMEM>>>(tok, w+OFF_WQ, nullptr, qkv,
                                               M, 1152, 384, nullptr, nullptr);

    kv_prep<<<dim3(LL/64, BB*NHH), 256>>>(kf, vf, kh, vh);

    attn_mma<<<dim3(LL/128, BB*NHH), 256, ATTN_SMEM>>>(q, kh, vh, rel_bias, attn);

    gemm_f16<3><<<dim3(384/64,  M/128), 256, GEMM_SMEM>>>(attn, w+OFF_WO, bo, ytok,
                                               M, 384, 384, x, ytokh);
    gemm_f16<1><<<dim3(1536/64, M/128), 256, GEMM_SMEM>>>(ytokh, w+OFF_FC1, fc1_b, nullptr,
                                               M, 1536, 384, nullptr, u1);
    gemm_f16<4><<<dim3(384/64,  M/128), 256, GEMM_SMEM>>>(u1, w+OFF_FC2, fc2_b, out,
                                               M, 384, 1536, ytok, nullptr);
}

// round 14
// speedup vs baseline: 3.1708x; 1.0294x over previous
#include <cuda_runtime.h>
#include <cuda_fp16.h>
#include <math.h>
#include <stdint.h>

// ---- problem constants ----
#define BB   8
#define CC   384
#define LL   1024
#define MM   (BB*LL)
#define NHH  8
#define DKK  48
#define DVV  48
#define CFF_ 1536
#define NBIAS_ 3969
#define LN_EPS_ 1e-5f

typedef __half fp16;

// ---- scratch ----
__device__ __align__(16) fp16  g_tok [MM*CC];
__device__ __align__(16) fp16  g_q16[MM*CC];          // [bh][l][d] fp16
__device__ __align__(16) fp16  g_kh [MM*CC];          // [bh][key][d] fp16
__device__ __align__(16) float g_vf [MM*CC];          // [bh][l][d] fp32
__device__ __align__(16) fp16  g_vh [MM*CC];          // [bh][d][tok] fp16
__device__ __align__(16) fp16  g_attn[MM*CC];
__device__ __align__(16) float g_ytok[MM*CC];
__device__ __align__(16) fp16  g_ytokh[MM*CC];
__device__ __align__(16) fp16  g_u1[MM*CFF_];

#define OFF_WQ  0
#define OFF_WO  442368
#define OFF_FC1 589824
#define OFF_FC2 1179648
#define NW_TOTAL 1769472
__device__ __align__(16) fp16 g_w[NW_TOTAL];

// single-instruction fp16x2 pack: result = (a low, b high), RN rounding
__device__ __forceinline__ uint32_t packf(float a, float b) {
    uint32_t r;
    asm("cvt.rn.f16x2.f32 %0, %1, %2;" : "=r"(r) : "f"(b), "f"(a));
    return r;
}
__device__ __forceinline__ uint32_t smem_u32(const void* p) {
    uint32_t a;
    asm("{ .reg .u64 t; cvta.to.shared.u64 t, %1; cvt.u32.u64 %0, t; }"
        : "=r"(a) : "l"(p));
    return a;
}
__device__ __forceinline__ void cp16(uint32_t saddr, const void* g) {
    asm volatile("cp.async.cg.shared.global [%0], [%1], 16;"
                 :: "r"(saddr), "l"(g) : "memory");
}
#define CP_COMMIT() asm volatile("cp.async.commit_group;" ::: "memory")
#define CP_WAIT1()  asm volatile("cp.async.wait_group 1;" ::: "memory")
#define CP_WAIT0()  asm volatile("cp.async.wait_group 0;" ::: "memory")

#define MMA_F16(c, a, b) \
    asm volatile("mma.sync.aligned.m16n8k16.row.col.f32.f16.f16.f32 " \
        "{%0,%1,%2,%3}, {%4,%5,%6,%7}, {%8,%9}, {%0,%1,%2,%3};" \
        : "+f"(c[0]), "+f"(c[1]), "+f"(c[2]), "+f"(c[3]) \
        : "r"(a[0]), "r"(a[1]), "r"(a[2]), "r"(a[3]), "r"(b[0]), "r"(b[1]))

// ============================================================
// Merged weight fp16 conversion (vectorized, 4 elems/thread)
// ============================================================
__global__ void conv_all(const float* __restrict__ Wq, const float* __restrict__ Wk,
                         const float* __restrict__ Wv, const float* __restrict__ Wo,
                         const float* __restrict__ f1, const float* __restrict__ f2,
                         fp16* __restrict__ w)
{
    int i4 = blockIdx.x * 256 + threadIdx.x;
    if (i4 >= NW_TOTAL/4) return;
    int i = i4 * 4;
    const float* src; int off;
    if (i < OFF_WO) {
        int m = i / 147456; off = i - m * 147456;
        src = (m == 0) ? Wq : (m == 1) ? Wk : Wv;
    } else if (i < OFF_FC1) { src = Wo; off = i - OFF_WO; }
    else if (i < OFF_FC2)   { src = f1; off = i - OFF_FC1; }
    else                    { src = f2; off = i - OFF_FC2; }
    float4 p = *(const float4*)&src[off];
    uint2 o;
    o.x = packf(p.x, p.y);
    o.y = packf(p.z, p.w);
    *(uint2*)&w[i] = o;
}

// ============================================================
// V prep only: transpose fp32 V -> fp16 [bh][d][tok]
// ============================================================
__global__ void v_prep(const float* __restrict__ vin, fp16* __restrict__ vh)
{
    const int bh = blockIdx.y;
    const int l0 = blockIdx.x * 64;
    const int tid = threadIdx.x;
    __shared__ float sv[48][65];

    const float* vb = vin + ((size_t)bh*1024 + l0)*48;
    for (int e = tid; e < 3072; e += 256) {
        int l = e / 48, d = e % 48;
        sv[d][l] = vb[e];
    }
    __syncthreads();
    uint32_t* vh32 = (uint32_t*)vh;
    for (int e = tid; e < 1536; e += 256) {
        int d = e >> 5, lp = e & 31;
        size_t i32 = ((((size_t)bh*48 + d)*1024 + l0) >> 1) + lp;
        vh32[i32] = packf(sv[d][2*lp], sv[d][2*lp + 1]);
    }
}

// ============================================================
// LayerNorm: single global read via smem tile; packed fp16 stores
// ============================================================
__global__ void ln_kernel(const float* __restrict__ x,
                          const float* __restrict__ gamma,
                          const float* __restrict__ beta,
                          fp16* __restrict__ tok)
{
    extern __shared__ __align__(16) float sbuf[];   // [384][33]
    __shared__ float redS [8][32];
    __shared__ float redS2[8][32];
    __shared__ float s_mu[32], s_inv[32];

    const int b  = blockIdx.y;
    const int l0 = blockIdx.x * 32;
    const int tid = threadIdx.x;
    const int lane = tid & 31;
    const int cy   = tid >> 5;

    for (int e = tid; e < CC*32; e += 256) {
        int c = e >> 5, t = e & 31;
        sbuf[c*33 + t] = x[((size_t)b*CC + c)*LL + l0 + t];
    }
    __syncthreads();

    float s = 0.f, s2 = 0.f;
    for (int c = cy; c < CC; c += 8) {
        float v = sbuf[c*33 + lane];
        s += v; s2 += v*v;
    }
    redS[cy][lane] = s; redS2[cy][lane] = s2;
    __syncthreads();
    if (cy == 0) {
        float ts = 0.f, ts2 = 0.f;
        #pragma unroll
        for (int i = 0; i < 8; i++) { ts += redS[i][lane]; ts2 += redS2[i][lane]; }
        float mu = ts * (1.0f/384.0f);
        float var = ts2 * (1.0f/384.0f) - mu*mu;
        s_mu[lane] = mu;
        s_inv[lane] = rsqrtf(var + LN_EPS_);
    }
    __syncthreads();

    uint32_t* tok32 = (uint32_t*)tok;
    for (int e = tid; e < CC*16; e += 256) {
        int t = e / 192, cp = e - t*192;
        int c = 2*cp;
        float mu = s_mu[t], inv = s_inv[t];
        float v0 = (sbuf[c*33 + t]     - mu) * inv * gamma[c]     + beta[c];
        float v1 = (sbuf[(c+1)*33 + t] - mu) * inv * gamma[c+1]   + beta[c+1];
        tok32[(((size_t)b*LL + l0 + t)*CC + c) >> 1] = packf(v0, v1);
    }
}

// ============================================================
// fp16 warp-MMA GEMM, double-buffered smem.
// MODE 2: fused QKV -> q,k fp16 packed; v fp32.
// ============================================================
template<int MODE>
__global__ __launch_bounds__(256)
void gemm_f16(const fp16* __restrict__ A,
              const fp16* __restrict__ W,
              const float* __restrict__ bias,
              float* __restrict__ Out,
              int M, int N, int K,
              const float* __restrict__ aux,
              fp16* __restrict__ outH)
{
    extern __shared__ __align__(16) uint32_t dsm[];

    const int tid  = threadIdx.x;
    const int m0   = blockIdx.y * 128;
    const int n0   = blockIdx.x * 64;
    const int warp = tid >> 5, lane = tid & 31;
    const int wm   = (warp >> 1) * 32;
    const int wn   = (warp & 1) * 32;
    const int gk   = lane & 3;
    const int gr   = lane >> 2;

    const int ar = tid >> 1, ak = (tid & 1) * 16;
    const int br = tid >> 2, bk = (tid & 3) * 8;

    const fp16* Ap = A + (size_t)(m0 + ar) * K + ak;
    const fp16* Bp = W + (size_t)(n0 + br) * K + bk;

    uint4 pa0 = *(const uint4*)Ap;
    uint4 pa1 = *(const uint4*)(Ap + 8);
    uint4 pb  = *(const uint4*)Bp;

    float acc[2][4][4];
    #pragma unroll
    for (int mi = 0; mi < 2; mi++)
        #pragma unroll
        for (int nj = 0; nj < 4; nj++)
            #pragma unroll
            for (int r = 0; r < 4; r++) acc[mi][nj][r] = 0.f;

    const int acol = (tid & 1) * 8;
    const int bcol = (tid & 3) * 4;

    {
        uint32_t* sA = dsm;
        uint32_t* sB = dsm + 2560;
        *(uint4*)&sA[ar*20 + acol]     = pa0;
        *(uint4*)&sA[ar*20 + acol + 4] = pa1;
        *(uint4*)&sB[br*20 + bcol]     = pb;
    }
    __syncthreads();

    int stage = 0;
    for (int k0 = 0; k0 < K; k0 += 32) {
        const bool more = (k0 + 32 < K);
        if (more) {
            Ap += 32; Bp += 32;
            pa0 = *(const uint4*)Ap;
            pa1 = *(const uint4*)(Ap + 8);
            pb  = *(const uint4*)Bp;
        }

        const uint32_t* sA = dsm + stage*3840;
        const uint32_t* sB = sA + 2560;

        #pragma unroll
        for (int ks = 0; ks < 2; ks++) {
            const int kb = ks*8 + gk;
            uint32_t af[2][4];
            #pragma unroll
            for (int mi = 0; mi < 2; mi++) {
                int mr = wm + mi*16 + gr;
                af[mi][0] = sA[(mr    )*20 + kb];
                af[mi][1] = sA[(mr + 8)*20 + kb];
                af[mi][2] = sA[(mr    )*20 + kb + 4];
                af[mi][3] = sA[(mr + 8)*20 + kb + 4];
            }
            #pragma unroll
            for (int nj = 0; nj < 4; nj++) {
                int nc = wn + nj*8 + gr;
                uint32_t bf[2] = { sB[nc*20 + kb], sB[nc*20 + kb + 4] };
                #pragma unroll
                for (int mi = 0; mi < 2; mi++)
                    MMA_F16(acc[mi][nj], af[mi], bf);
            }
        }

        if (more) {
            uint32_t* nA = dsm + (stage^1)*3840;
            uint32_t* nB = nA + 2560;
            *(uint4*)&nA[ar*20 + acol]     = pa0;
            *(uint4*)&nA[ar*20 + acol + 4] = pa1;
            *(uint4*)&nB[br*20 + bcol]     = pb;
            stage ^= 1;
            __syncthreads();
        }
    }

    if (MODE == 2) {
        // fused QKV: q,k packed fp16; v fp32. col pairs (2gk, 2gk+1).
        uint32_t* q32 = (uint32_t*)g_q16;
        uint32_t* k32 = (uint32_t*)g_kh;
        #pragma unroll
        for (int mi = 0; mi < 2; mi++) {
            #pragma unroll
            for (int nj = 0; nj < 4; nj++) {
                int c0  = n0 + wn + nj*8 + 2*gk;
                int mat = c0 / 384;
                int cm  = c0 - mat * 384;
                int h = cm / 48, d0 = cm % 48;
                #pragma unroll
                for (int half = 0; half < 2; half++) {
                    int row = m0 + wm + mi*16 + gr + (half ? 8 : 0);
                    int b = row >> 10, l = row & 1023;
                    int bh = b*8 + h;
                    float v0 = acc[mi][nj][half*2 + 0];
                    float v1 = acc[mi][nj][half*2 + 1];
                    size_t ei = ((size_t)bh*1024 + l)*48 + d0;
                    if (mat == 0)      q32[ei >> 1] = packf(v0, v1);
                    else if (mat == 1) k32[ei >> 1] = packf(v0, v1);
                    else *(float2*)&Out[ei] = make_float2(v0, v1);
                }
            }
        }
        return;
    }

    #pragma unroll
    for (int mi = 0; mi < 2; mi++) {
        #pragma unroll
        for (int nj = 0; nj < 4; nj++) {
            #pragma unroll
            for (int r = 0; r < 4; r++) {
                int row = m0 + wm + mi*16 + gr + ((r & 2) ? 8 : 0);
                int col = n0 + wn + nj*8 + 2*gk + (r & 1);
                int b = row >> 10, l = row & 1023;
                float v = acc[mi][nj][r] + (bias ? bias[col] : 0.f);
                if (MODE == 3) {
                    v += aux[(size_t)(b*384 + col) * 1024 + l];
                    size_t idx = (size_t)row * 384 + col;
                    Out[idx] = v;
                    outH[idx] = __float2half(v);
                } else if (MODE == 1) {
                    v = 0.5f * v * (1.0f + erff(v * 0.70710678118654752f));
                    outH[(size_t)row * N + col] = __float2half(v);
                } else { // MODE 4
                    Out[(size_t)(b*384 + col) * 1024 + l] =
                        v + aux[(size_t)row * 384 + col];
                }
            }
        }
    }
}

// ============================================================
// FA2 fp16 attention: cp.async K/V double-buffer, bias in smem,
// fp16 Q loaded directly as packed fragments.
// ============================================================
#define AT_STAGE_U32 3520
#define AT_K_OFF     0
#define AT_V_OFF     1792

__global__ __launch_bounds__(256, 2)
void attn_mma(const fp16* __restrict__ q16,
              const fp16* __restrict__ khg,
              const fp16* __restrict__ vhg,
              const float* __restrict__ rel_bias,
              fp16* __restrict__ attn_out)
{
    extern __shared__ __align__(16) uint32_t asm_[];
    __shared__ float sBias[NBIAS_];

    const int b  = blockIdx.y >> 3;
    const int h  = blockIdx.y & 7;
    const int bh = b*8 + h;
    const int q0 = blockIdx.x * 128;
    const int tid  = threadIdx.x;
    const int warp = tid >> 5, lane = tid & 31;
    const int gid  = lane >> 2;
    const int tig  = lane & 3;

    const uint32_t* qbase32 = (const uint32_t*)(q16 + (size_t)bh * LL * 48);
    const uint4* kh4 = (const uint4*)(khg + (size_t)bh * LL * 48);
    const fp16* vhb = vhg + (size_t)bh * 48 * 1024;
    const float* biasrow = rel_bias + (size_t)h * NBIAS_;

    const uint32_t sbase = smem_u32(asm_);

    for (int e = tid; e < NBIAS_; e += 256) sBias[e] = biasrow[e];

    const int qrow0 = q0 + warp*16 + gid;
    const int qrow1 = qrow0 + 8;
    const int ly0 = qrow0 >> 5, lx0 = qrow0 & 31;
    const int ly1 = qrow1 >> 5, lx1 = qrow1 & 31;

    uint32_t qf[3][4];
    #pragma unroll
    for (int kp = 0; kp < 3; kp++) {
        int d0 = 16*kp + 2*tig;
        #pragma unroll
        for (int rr = 0; rr < 2; rr++) {
            int row = rr ? qrow1 : qrow0;
            qf[kp][rr]   = qbase32[((size_t)row*48 + d0) >> 1];
            qf[kp][rr+2] = qbase32[((size_t)row*48 + d0 + 8) >> 1];
        }
    }

    float m0r = -1e30f, m1r = -1e30f, s0r = 0.f, s1r = 0.f;
    float o[6][4];
    #pragma unroll
    for (int nt = 0; nt < 6; nt++)
        #pragma unroll
        for (int r = 0; r < 4; r++) o[nt][r] = 0.f;

    auto issue = [&](int mc, int buf) {
        uint32_t kb = sbase + (buf*AT_STAGE_U32 + AT_K_OFF)*4;
        uint32_t vb = sbase + (buf*AT_STAGE_U32 + AT_V_OFF)*4;
        for (int e = tid; e < 384; e += 256) {
            int r = e / 6, j = e - r*6;
            cp16(kb + (r*28 + 4*j)*4, kh4 + (size_t)(mc + r)*6 + j);
        }
        for (int e = tid; e < 384; e += 256) {
            int d = e >> 3, j = e & 7;
            cp16(vb + (d*36 + 4*j)*4, (const uint4*)(vhb + (size_t)d*1024 + mc) + j);
        }
    };

    issue(0, 0);
    CP_COMMIT();

    for (int ic = 0; ic < 16; ic++) {
        const int mc = ic * 64;
        const int buf = ic & 1;

        if (ic + 1 < 16) {
            issue(mc + 64, buf ^ 1);
            CP_COMMIT();
            CP_WAIT1();
        } else {
            CP_WAIT0();
        }
        __syncthreads();

        const uint32_t* sK = asm_ + buf*AT_STAGE_U32 + AT_K_OFF;
        const uint32_t* sV = asm_ + buf*AT_STAGE_U32 + AT_V_OFF;

        float sc[8][4];
        #pragma unroll
        for (int t = 0; t < 8; t++)
            #pragma unroll
            for (int r = 0; r < 4; r++) sc[t][r] = 0.f;

        #pragma unroll
        for (int kp = 0; kp < 3; kp++) {
            #pragma unroll
            for (int t = 0; t < 8; t++) {
                int key = 8*t + gid;
                int dp  = 8*kp + tig;
                uint32_t bf[2] = { sK[key*28 + dp], sK[key*28 + dp + 4] };
                MMA_F16(sc[t], qf[kp], bf);
            }
        }

        float rm0 = -1e30f, rm1 = -1e30f;
        #pragma unroll
        for (int t = 0; t < 8; t++) {
            int ma = mc + 8*t + 2*tig, mb = ma + 1;
            int may = ma >> 5, max_ = ma & 31;
            int mby = mb >> 5, mbx = mb & 31;
            sc[t][0] += sBias[(may - ly0 + 32)*32 + (max_ - lx0 + 32)];
            sc[t][1] += sBias[(mby - ly0 + 32)*32 + (mbx - lx0 + 32)];
            sc[t][2] += sBias[(may - ly1 + 32)*32 + (max_ - lx1 + 32)];
            sc[t][3] += sBias[(mby - ly1 + 32)*32 + (mbx - lx1 + 32)];
            rm0 = fmaxf(rm0, fmaxf(sc[t][0], sc[t][1]));
            rm1 = fmaxf(rm1, fmaxf(sc[t][2], sc[t][3]));
        }
        rm0 = fmaxf(rm0, __shfl_xor_sync(0xffffffffu, rm0, 1));
        rm0 = fmaxf(rm0, __shfl_xor_sync(0xffffffffu, rm0, 2));
        rm1 = fmaxf(rm1, __shfl_xor_sync(0xffffffffu, rm1, 1));
        rm1 = fmaxf(rm1, __shfl_xor_sync(0xffffffffu, rm1, 2));

        float nm0 = fmaxf(m0r, rm0), nm1 = fmaxf(m1r, rm1);
        float al0 = __expf(m0r - nm0), al1 = __expf(m1r - nm1);
        m0r = nm0; m1r = nm1;

        #pragma unroll
        for (int nt = 0; nt < 6; nt++) {
            o[nt][0] *= al0; o[nt][1] *= al0;
            o[nt][2] *= al1; o[nt][3] *= al1;
        }

        float ps0 = 0.f, ps1 = 0.f;
        #pragma unroll
        for (int kp = 0; kp < 4; kp++) {
            uint32_t pf[4];
            #pragma unroll
            for (int tt = 0; tt < 2; tt++) {
                int t = 2*kp + tt;
                float p0 = __expf(sc[t][0] - nm0);
                float p1 = __expf(sc[t][1] - nm0);
                float p2 = __expf(sc[t][2] - nm1);
                float p3 = __expf(sc[t][3] - nm1);
                ps0 += p0 + p1; ps1 += p2 + p3;
                pf[2*tt]   = packf(p0, p1);
                pf[2*tt+1] = packf(p2, p3);
            }
            #pragma unroll
            for (int nt = 0; nt < 6; nt++) {
                int d  = 8*nt + gid;
                int mp = 8*kp + tig;
                uint32_t bf[2] = { sV[d*36 + mp], sV[d*36 + mp + 4] };
                MMA_F16(o[nt], pf, bf);
            }
        }
        ps0 += __shfl_xor_sync(0xffffffffu, ps0, 1);
        ps0 += __shfl_xor_sync(0xffffffffu, ps0, 2);
        ps1 += __shfl_xor_sync(0xffffffffu, ps1, 1);
        ps1 += __shfl_xor_sync(0xffffffffu, ps1, 2);
        s0r = s0r * al0 + ps0;
        s1r = s1r * al1 + ps1;

        __syncthreads();
    }

    float inv0 = 1.0f / s0r, inv1 = 1.0f / s1r;
    uint32_t* out32 = (uint32_t*)attn_out;
    #pragma unroll
    for (int nt = 0; nt < 6; nt++) {
        int d = 8*nt + 2*tig;
        size_t i0 = ((size_t)(b*LL + qrow0) * 384 + h*48 + d) >> 1;
        size_t i1 = ((size_t)(b*LL + qrow1) * 384 + h*48 + d) >> 1;
        out32[i0] = packf(o[nt][0]*inv0, o[nt][1]*inv0);
        out32[i1] = packf(o[nt][2]*inv1, o[nt][3]*inv1);
    }
}

// ============================================================
// launch
// ============================================================
extern "C" void kernel_launch(void* const* d_in, const int* in_sizes, int n_in,
                              void* d_out, int out_size)
{
    (void)in_sizes; (void)n_in; (void)out_size;
    const float* x        = (const float*)d_in[0];
    const float* gamma    = (const float*)d_in[1];
    const float* beta     = (const float*)d_in[2];
    const float* Wq       = (const float*)d_in[3];
    const float* Wk       = (const float*)d_in[4];
    const float* Wv       = (const float*)d_in[5];
    const float* Wo       = (const float*)d_in[6];
    const float* bo       = (const float*)d_in[7];
    const float* rel_bias = (const float*)d_in[8];
    const float* fc1_w    = (const float*)d_in[9];
    const float* fc1_b    = (const float*)d_in[10];
    const float* fc2_w    = (const float*)d_in[11];
    const float* fc2_b    = (const float*)d_in[12];
    float* out = (float*)d_out;

    fp16 *tok, *attn, *ytokh, *u1, *w, *q16, *kh, *vh;
    float *vf, *ytok;
    cudaGetSymbolAddress((void**)&tok,   g_tok);
    cudaGetSymbolAddress((void**)&q16,   g_q16);
    cudaGetSymbolAddress((void**)&kh,    g_kh);
    cudaGetSymbolAddress((void**)&vf,    g_vf);
    cudaGetSymbolAddress((void**)&vh,    g_vh);
    cudaGetSymbolAddress((void**)&attn,  g_attn);
    cudaGetSymbolAddress((void**)&ytok,  g_ytok);
    cudaGetSymbolAddress((void**)&ytokh, g_ytokh);
    cudaGetSymbolAddress((void**)&u1,    g_u1);
    cudaGetSymbolAddress((void**)&w,     g_w);

    const int M = MM;
    const int GEMM_SMEM = 30720;
    const int ATTN_SMEM = 28160;
    const int LN_SMEM   = 384*33*4;

    cudaFuncSetAttribute(ln_kernel, cudaFuncAttributeMaxDynamicSharedMemorySize, LN_SMEM);

    conv_all<<<(NW_TOTAL/4 + 255)/256, 256>>>(Wq, Wk, Wv, Wo, fc1_w, fc2_w, w);

    ln_kernel<<<dim3(LL/32, BB), 256, LN_SMEM>>>(x, gamma, beta, tok);

    // fused QKV: q,k written fp16 packed directly; v fp32 (Out = vf)
    gemm_f16<2><<<dim3(1152/64, M/128), 256, GEMM_SMEM>>>(tok, w+OFF_WQ, nullptr, vf,
                                               M, 1152, 384, nullptr, nullptr);

    v_prep<<<dim3(LL/64, BB*NHH), 256>>>(vf, vh);

    attn_mma<<<dim3(LL/128, BB*NHH), 256, ATTN_SMEM>>>(q16, kh, vh, rel_bias, attn);

    gemm_f16<3><<<dim3(384/64,  M/128), 256, GEMM_SMEM>>>(attn, w+OFF_WO, bo, ytok,
                                               M, 384, 384, x, ytokh);
    gemm_f16<1><<<dim3(1536/64, M/128), 256, GEMM_SMEM>>>(ytokh, w+OFF_FC1, fc1_b, nullptr,
                                               M, 1536, 384, nullptr, u1);
    gemm_f16<4><<<dim3(384/64,  M/128), 256, GEMM_SMEM>>>(u1, w+OFF_FC2, fc2_b, out,
                                               M, 384, 1536, ytok, nullptr);
}

// round 16
// speedup vs baseline: 3.3530x; 1.0575x over previous
#include <cuda_runtime.h>
#include <cuda_fp16.h>
#include <math.h>
#include <stdint.h>

// ---- problem constants ----
#define BB   8
#define CC   384
#define LL   1024
#define MM   (BB*LL)
#define NHH  8
#define DKK  48
#define DVV  48
#define CFF_ 1536
#define NBIAS_ 3969
#define LN_EPS_ 1e-5f

typedef __half fp16;

// ---- scratch ----
__device__ __align__(16) fp16  g_tok [MM*CC];
__device__ __align__(16) fp16  g_q16[MM*CC];          // [bh][l][d] fp16
__device__ __align__(16) fp16  g_kh [MM*CC];          // [bh][key][d] fp16
__device__ __align__(16) float g_vf [MM*CC];          // [bh][l][d] fp32
__device__ __align__(16) fp16  g_vh [MM*CC];          // [bh][d][tok] fp16
__device__ __align__(16) fp16  g_attn[MM*CC];
__device__ __align__(16) float g_ytok[MM*CC];
__device__ __align__(16) fp16  g_ytokh[MM*CC];
__device__ __align__(16) fp16  g_u1[MM*CFF_];

#define OFF_WQ  0
#define OFF_WO  442368
#define OFF_FC1 589824
#define OFF_FC2 1179648
#define NW_TOTAL 1769472
__device__ __align__(16) fp16 g_w[NW_TOTAL];

// single-instruction fp16x2 pack (RN)
__device__ __forceinline__ uint32_t packf(float a, float b) {
    uint32_t r;
    asm("cvt.rn.f16x2.f32 %0, %1, %2;" : "=r"(r) : "f"(b), "f"(a));
    return r;
}
__device__ __forceinline__ uint32_t smem_u32(const void* p) {
    uint32_t a;
    asm("{ .reg .u64 t; cvta.to.shared.u64 t, %1; cvt.u32.u64 %0, t; }"
        : "=r"(a) : "l"(p));
    return a;
}
__device__ __forceinline__ void cp16(uint32_t saddr, const void* g) {
    asm volatile("cp.async.cg.shared.global [%0], [%1], 16;"
                 :: "r"(saddr), "l"(g) : "memory");
}
#define CP_COMMIT() asm volatile("cp.async.commit_group;" ::: "memory")
#define CP_WAIT1()  asm volatile("cp.async.wait_group 1;" ::: "memory")
#define CP_WAIT0()  asm volatile("cp.async.wait_group 0;" ::: "memory")

#define MMA_F16(c, a, b) \
    asm volatile("mma.sync.aligned.m16n8k16.row.col.f32.f16.f16.f32 " \
        "{%0,%1,%2,%3}, {%4,%5,%6,%7}, {%8,%9}, {%0,%1,%2,%3};" \
        : "+f"((c)[0]), "+f"((c)[1]), "+f"((c)[2]), "+f"((c)[3]) \
        : "r"((a)[0]), "r"((a)[1]), "r"((a)[2]), "r"((a)[3]), \
          "r"((b)[0]), "r"((b)[1]))

// warp-collective 4x(8x8 b16) matrix load; lane i supplies row i%8 of matrix i/8
#define LDSM4(r, addr) \
    asm volatile("ldmatrix.sync.aligned.m8n8.x4.shared.b16 {%0,%1,%2,%3}, [%4];" \
        : "=r"((r)[0]), "=r"((r)[1]), "=r"((r)[2]), "=r"((r)[3]) : "r"(addr))

// ============================================================
// Merged weight fp16 conversion (vectorized)
// ============================================================
__global__ void conv_all(const float* __restrict__ Wq, const float* __restrict__ Wk,
                         const float* __restrict__ Wv, const float* __restrict__ Wo,
                         const float* __restrict__ f1, const float* __restrict__ f2,
                         fp16* __restrict__ w)
{
    int i4 = blockIdx.x * 256 + threadIdx.x;
    if (i4 >= NW_TOTAL/4) return;
    int i = i4 * 4;
    const float* src; int off;
    if (i < OFF_WO) {
        int m = i / 147456; off = i - m * 147456;
        src = (m == 0) ? Wq : (m == 1) ? Wk : Wv;
    } else if (i < OFF_FC1) { src = Wo; off = i - OFF_WO; }
    else if (i < OFF_FC2)   { src = f1; off = i - OFF_FC1; }
    else                    { src = f2; off = i - OFF_FC2; }
    float4 p = *(const float4*)&src[off];
    uint2 o;
    o.x = packf(p.x, p.y);
    o.y = packf(p.z, p.w);
    *(uint2*)&w[i] = o;
}

// ============================================================
// V prep: transpose fp32 V -> fp16 [bh][d][tok]
// ============================================================
__global__ void v_prep(const float* __restrict__ vin, fp16* __restrict__ vh)
{
    const int bh = blockIdx.y;
    const int l0 = blockIdx.x * 64;
    const int tid = threadIdx.x;
    __shared__ float sv[48][65];

    const float* vb = vin + ((size_t)bh*1024 + l0)*48;
    for (int e = tid; e < 3072; e += 256) {
        int l = e / 48, d = e % 48;
        sv[d][l] = vb[e];
    }
    __syncthreads();
    uint32_t* vh32 = (uint32_t*)vh;
    for (int e = tid; e < 1536; e += 256) {
        int d = e >> 5, lp = e & 31;
        size_t i32 = ((((size_t)bh*48 + d)*1024 + l0) >> 1) + lp;
        vh32[i32] = packf(sv[d][2*lp], sv[d][2*lp + 1]);
    }
}

// ============================================================
// LayerNorm (unchanged)
// ============================================================
__global__ void ln_kernel(const float* __restrict__ x,
                          const float* __restrict__ gamma,
                          const float* __restrict__ beta,
                          fp16* __restrict__ tok)
{
    extern __shared__ __align__(16) float sbuf[];   // [384][33]
    __shared__ float redS [8][32];
    __shared__ float redS2[8][32];
    __shared__ float s_mu[32], s_inv[32];

    const int b  = blockIdx.y;
    const int l0 = blockIdx.x * 32;
    const int tid = threadIdx.x;
    const int lane = tid & 31;
    const int cy   = tid >> 5;

    for (int e = tid; e < CC*32; e += 256) {
        int c = e >> 5, t = e & 31;
        sbuf[c*33 + t] = x[((size_t)b*CC + c)*LL + l0 + t];
    }
    __syncthreads();

    float s = 0.f, s2 = 0.f;
    for (int c = cy; c < CC; c += 8) {
        float v = sbuf[c*33 + lane];
        s += v; s2 += v*v;
    }
    redS[cy][lane] = s; redS2[cy][lane] = s2;
    __syncthreads();
    if (cy == 0) {
        float ts = 0.f, ts2 = 0.f;
        #pragma unroll
        for (int i = 0; i < 8; i++) { ts += redS[i][lane]; ts2 += redS2[i][lane]; }
        float mu = ts * (1.0f/384.0f);
        float var = ts2 * (1.0f/384.0f) - mu*mu;
        s_mu[lane] = mu;
        s_inv[lane] = rsqrtf(var + LN_EPS_);
    }
    __syncthreads();

    uint32_t* tok32 = (uint32_t*)tok;
    for (int e = tid; e < CC*16; e += 256) {
        int t = e / 192, cp = e - t*192;
        int c = 2*cp;
        float mu = s_mu[t], inv = s_inv[t];
        float v0 = (sbuf[c*33 + t]     - mu) * inv * gamma[c]     + beta[c];
        float v1 = (sbuf[(c+1)*33 + t] - mu) * inv * gamma[c+1]   + beta[c+1];
        tok32[(((size_t)b*LL + l0 + t)*CC + c) >> 1] = packf(v0, v1);
    }
}

// ============================================================
// fp16 warp-MMA GEMM, double-buffered smem + ldmatrix fragment loads.
// MODE 2: fused QKV -> q,k fp16 packed; v fp32.
// ============================================================
template<int MODE>
__global__ __launch_bounds__(256)
void gemm_f16(const fp16* __restrict__ A,
              const fp16* __restrict__ W,
              const float* __restrict__ bias,
              float* __restrict__ Out,
              int M, int N, int K,
              const float* __restrict__ aux,
              fp16* __restrict__ outH)
{
    extern __shared__ __align__(16) uint32_t dsm[];
    const uint32_t sbase = smem_u32(dsm);

    const int tid  = threadIdx.x;
    const int m0   = blockIdx.y * 128;
    const int n0   = blockIdx.x * 64;
    const int warp = tid >> 5, lane = tid & 31;
    const int wm   = (warp >> 1) * 32;
    const int wn   = (warp & 1) * 32;
    const int gk   = lane & 3;
    const int gr   = lane >> 2;

    // ldmatrix per-lane addressing: j = matrix index, rl = row in matrix
    const int j  = lane >> 3;
    const int rl = lane & 7;
    const uint32_t aoff0 = ((uint32_t)(wm + (j&1)*8 + rl)*20 + (j>>1)*4)*4;
    const uint32_t aoff1 = aoff0 + 16*20*4;
    const uint32_t boff0 = 2560*4 + ((uint32_t)(wn + (j>>1)*8 + rl)*20 + (j&1)*4)*4;
    const uint32_t boff1 = boff0 + 16*20*4;

    const int ar = tid >> 1, ak = (tid & 1) * 16;
    const int br = tid >> 2, bk = (tid & 3) * 8;

    const fp16* Ap = A + (size_t)(m0 + ar) * K + ak;
    const fp16* Bp = W + (size_t)(n0 + br) * K + bk;

    uint4 pa0 = *(const uint4*)Ap;
    uint4 pa1 = *(const uint4*)(Ap + 8);
    uint4 pb  = *(const uint4*)Bp;

    float acc[2][4][4];
    #pragma unroll
    for (int mi = 0; mi < 2; mi++)
        #pragma unroll
        for (int nj = 0; nj < 4; nj++)
            #pragma unroll
            for (int r = 0; r < 4; r++) acc[mi][nj][r] = 0.f;

    const int acol = (tid & 1) * 8;
    const int bcol = (tid & 3) * 4;

    {
        uint32_t* sA = dsm;
        uint32_t* sB = dsm + 2560;
        *(uint4*)&sA[ar*20 + acol]     = pa0;
        *(uint4*)&sA[ar*20 + acol + 4] = pa1;
        *(uint4*)&sB[br*20 + bcol]     = pb;
    }
    __syncthreads();

    int stage = 0;
    for (int k0 = 0; k0 < K; k0 += 32) {
        const bool more = (k0 + 32 < K);
        if (more) {
            Ap += 32; Bp += 32;
            pa0 = *(const uint4*)Ap;
            pa1 = *(const uint4*)(Ap + 8);
            pb  = *(const uint4*)Bp;
        }

        const uint32_t sstg = sbase + stage*15360;

        #pragma unroll
        for (int ks = 0; ks < 2; ks++) {
            const uint32_t kb = ks*32;
            uint32_t a0[4], a1[4], b0[4], b1[4];
            LDSM4(a0, sstg + aoff0 + kb);
            LDSM4(a1, sstg + aoff1 + kb);
            LDSM4(b0, sstg + boff0 + kb);
            LDSM4(b1, sstg + boff1 + kb);
            MMA_F16(acc[0][0], a0, b0);      MMA_F16(acc[1][0], a1, b0);
            MMA_F16(acc[0][1], a0, &b0[2]);  MMA_F16(acc[1][1], a1, &b0[2]);
            MMA_F16(acc[0][2], a0, b1);      MMA_F16(acc[1][2], a1, b1);
            MMA_F16(acc[0][3], a0, &b1[2]);  MMA_F16(acc[1][3], a1, &b1[2]);
        }

        if (more) {
            uint32_t* nA = dsm + (stage^1)*3840;
            uint32_t* nB = nA + 2560;
            *(uint4*)&nA[ar*20 + acol]     = pa0;
            *(uint4*)&nA[ar*20 + acol + 4] = pa1;
            *(uint4*)&nB[br*20 + bcol]     = pb;
            stage ^= 1;
            __syncthreads();
        }
    }

    if (MODE == 2) {
        uint32_t* q32 = (uint32_t*)g_q16;
        uint32_t* k32 = (uint32_t*)g_kh;
        #pragma unroll
        for (int mi = 0; mi < 2; mi++) {
            #pragma unroll
            for (int nj = 0; nj < 4; nj++) {
                int c0  = n0 + wn + nj*8 + 2*gk;
                int mat = c0 / 384;
                int cm  = c0 - mat * 384;
                int h = cm / 48, d0 = cm % 48;
                #pragma unroll
                for (int half = 0; half < 2; half++) {
                    int row = m0 + wm + mi*16 + gr + (half ? 8 : 0);
                    int b = row >> 10, l = row & 1023;
                    int bh = b*8 + h;
                    float v0 = acc[mi][nj][half*2 + 0];
                    float v1 = acc[mi][nj][half*2 + 1];
                    size_t ei = ((size_t)bh*1024 + l)*48 + d0;
                    if (mat == 0)      q32[ei >> 1] = packf(v0, v1);
                    else if (mat == 1) k32[ei >> 1] = packf(v0, v1);
                    else *(float2*)&Out[ei] = make_float2(v0, v1);
                }
            }
        }
        return;
    }

    #pragma unroll
    for (int mi = 0; mi < 2; mi++) {
        #pragma unroll
        for (int nj = 0; nj < 4; nj++) {
            #pragma unroll
            for (int r = 0; r < 4; r++) {
                int row = m0 + wm + mi*16 + gr + ((r & 2) ? 8 : 0);
                int col = n0 + wn + nj*8 + 2*gk + (r & 1);
                int b = row >> 10, l = row & 1023;
                float v = acc[mi][nj][r] + (bias ? bias[col] : 0.f);
                if (MODE == 3) {
                    v += aux[(size_t)(b*384 + col) * 1024 + l];
                    size_t idx = (size_t)row * 384 + col;
                    Out[idx] = v;
                    outH[idx] = __float2half(v);
                } else if (MODE == 1) {
                    v = 0.5f * v * (1.0f + erff(v * 0.70710678118654752f));
                    outH[(size_t)row * N + col] = __float2half(v);
                } else { // MODE 4
                    Out[(size_t)(b*384 + col) * 1024 + l] =
                        v + aux[(size_t)row * 384 + col];
                }
            }
        }
    }
}

// ============================================================
// FA2 fp16 attention: cp.async K/V double-buffer, bias in smem,
// ldmatrix K/V fragment loads.
// ============================================================
#define AT_STAGE_U32 3520
#define AT_K_OFF     0
#define AT_V_OFF     1792

__global__ __launch_bounds__(256, 2)
void attn_mma(const fp16* __restrict__ q16,
              const fp16* __restrict__ khg,
              const fp16* __restrict__ vhg,
              const float* __restrict__ rel_bias,
              fp16* __restrict__ attn_out)
{
    extern __shared__ __align__(16) uint32_t asm_[];
    __shared__ float sBias[NBIAS_];

    const int b  = blockIdx.y >> 3;
    const int h  = blockIdx.y & 7;
    const int bh = b*8 + h;
    const int q0 = blockIdx.x * 128;
    const int tid  = threadIdx.x;
    const int warp = tid >> 5, lane = tid & 31;
    const int gid  = lane >> 2;
    const int tig  = lane & 3;

    const uint32_t* qbase32 = (const uint32_t*)(q16 + (size_t)bh * LL * 48);
    const uint4* kh4 = (const uint4*)(khg + (size_t)bh * LL * 48);
    const fp16* vhb = vhg + (size_t)bh * 48 * 1024;
    const float* biasrow = rel_bias + (size_t)h * NBIAS_;

    const uint32_t sbase = smem_u32(asm_);

    for (int e = tid; e < NBIAS_; e += 256) sBias[e] = biasrow[e];

    // ldmatrix per-lane offsets
    const int j  = lane >> 3;
    const int rl = lane & 7;
    uint32_t koff[4], voff[3];
    #pragma unroll
    for (int tp = 0; tp < 4; tp++)
        koff[tp] = ((uint32_t)(16*tp + (j>>1)*8 + rl)*28 + (j&1)*4)*4;
    #pragma unroll
    for (int np = 0; np < 3; np++)
        voff[np] = AT_V_OFF*4 + ((uint32_t)(16*np + (j>>1)*8 + rl)*36 + (j&1)*4)*4;

    const int qrow0 = q0 + warp*16 + gid;
    const int qrow1 = qrow0 + 8;
    const int ly0 = qrow0 >> 5, lx0 = qrow0 & 31;
    const int ly1 = qrow1 >> 5, lx1 = qrow1 & 31;

    uint32_t qf[3][4];
    #pragma unroll
    for (int kp = 0; kp < 3; kp++) {
        int d0 = 16*kp + 2*tig;
        #pragma unroll
        for (int rr = 0; rr < 2; rr++) {
            int row = rr ? qrow1 : qrow0;
            qf[kp][rr]   = qbase32[((size_t)row*48 + d0) >> 1];
            qf[kp][rr+2] = qbase32[((size_t)row*48 + d0 + 8) >> 1];
        }
    }

    float m0r = -1e30f, m1r = -1e30f, s0r = 0.f, s1r = 0.f;
    float o[6][4];
    #pragma unroll
    for (int nt = 0; nt < 6; nt++)
        #pragma unroll
        for (int r = 0; r < 4; r++) o[nt][r] = 0.f;

    auto issue = [&](int mc, int buf) {
        uint32_t kb = sbase + (buf*AT_STAGE_U32 + AT_K_OFF)*4;
        uint32_t vb = sbase + (buf*AT_STAGE_U32 + AT_V_OFF)*4;
        for (int e = tid; e < 384; e += 256) {
            int r = e / 6, jj = e - r*6;
            cp16(kb + (r*28 + 4*jj)*4, kh4 + (size_t)(mc + r)*6 + jj);
        }
        for (int e = tid; e < 384; e += 256) {
            int d = e >> 3, jj = e & 7;
            cp16(vb + (d*36 + 4*jj)*4, (const uint4*)(vhb + (size_t)d*1024 + mc) + jj);
        }
    };

    issue(0, 0);
    CP_COMMIT();

    for (int ic = 0; ic < 16; ic++) {
        const int mc = ic * 64;
        const int buf = ic & 1;

        if (ic + 1 < 16) {
            issue(mc + 64, buf ^ 1);
            CP_COMMIT();
            CP_WAIT1();
        } else {
            CP_WAIT0();
        }
        __syncthreads();

        const uint32_t bufoff = sbase + buf*(AT_STAGE_U32*4);

        // ---- S = Q K^T via ldmatrix ----
        float sc[8][4];
        #pragma unroll
        for (int t = 0; t < 8; t++)
            #pragma unroll
            for (int r = 0; r < 4; r++) sc[t][r] = 0.f;

        #pragma unroll
        for (int kp = 0; kp < 3; kp++) {
            #pragma unroll
            for (int tp = 0; tp < 4; tp++) {
                uint32_t kk[4];
                LDSM4(kk, bufoff + koff[tp] + kp*32);
                MMA_F16(sc[2*tp],     qf[kp], kk);
                MMA_F16(sc[2*tp + 1], qf[kp], &kk[2]);
            }
        }

        // ---- bias + row max ----
        float rm0 = -1e30f, rm1 = -1e30f;
        #pragma unroll
        for (int t = 0; t < 8; t++) {
            int ma = mc + 8*t + 2*tig, mb = ma + 1;
            int may = ma >> 5, max_ = ma & 31;
            int mby = mb >> 5, mbx = mb & 31;
            sc[t][0] += sBias[(may - ly0 + 32)*32 + (max_ - lx0 + 32)];
            sc[t][1] += sBias[(mby - ly0 + 32)*32 + (mbx - lx0 + 32)];
            sc[t][2] += sBias[(may - ly1 + 32)*32 + (max_ - lx1 + 32)];
            sc[t][3] += sBias[(mby - ly1 + 32)*32 + (mbx - lx1 + 32)];
            rm0 = fmaxf(rm0, fmaxf(sc[t][0], sc[t][1]));
            rm1 = fmaxf(rm1, fmaxf(sc[t][2], sc[t][3]));
        }
        rm0 = fmaxf(rm0, __shfl_xor_sync(0xffffffffu, rm0, 1));
        rm0 = fmaxf(rm0, __shfl_xor_sync(0xffffffffu, rm0, 2));
        rm1 = fmaxf(rm1, __shfl_xor_sync(0xffffffffu, rm1, 1));
        rm1 = fmaxf(rm1, __shfl_xor_sync(0xffffffffu, rm1, 2));

        float nm0 = fmaxf(m0r, rm0), nm1 = fmaxf(m1r, rm1);
        float al0 = __expf(m0r - nm0), al1 = __expf(m1r - nm1);
        m0r = nm0; m1r = nm1;

        #pragma unroll
        for (int nt = 0; nt < 6; nt++) {
            o[nt][0] *= al0; o[nt][1] *= al0;
            o[nt][2] *= al1; o[nt][3] *= al1;
        }

        // ---- fused exp/pack + PV via ldmatrix ----
        float ps0 = 0.f, ps1 = 0.f;
        #pragma unroll
        for (int kp = 0; kp < 4; kp++) {
            uint32_t pf[4];
            #pragma unroll
            for (int tt = 0; tt < 2; tt++) {
                int t = 2*kp + tt;
                float p0 = __expf(sc[t][0] - nm0);
                float p1 = __expf(sc[t][1] - nm0);
                float p2 = __expf(sc[t][2] - nm1);
                float p3 = __expf(sc[t][3] - nm1);
                ps0 += p0 + p1; ps1 += p2 + p3;
                pf[2*tt]   = packf(p0, p1);
                pf[2*tt+1] = packf(p2, p3);
            }
            #pragma unroll
            for (int np = 0; np < 3; np++) {
                uint32_t vv[4];
                LDSM4(vv, bufoff + voff[np] + kp*32);
                MMA_F16(o[2*np],     pf, vv);
                MMA_F16(o[2*np + 1], pf, &vv[2]);
            }
        }
        ps0 += __shfl_xor_sync(0xffffffffu, ps0, 1);
        ps0 += __shfl_xor_sync(0xffffffffu, ps0, 2);
        ps1 += __shfl_xor_sync(0xffffffffu, ps1, 1);
        ps1 += __shfl_xor_sync(0xffffffffu, ps1, 2);
        s0r = s0r * al0 + ps0;
        s1r = s1r * al1 + ps1;

        __syncthreads();
    }

    float inv0 = 1.0f / s0r, inv1 = 1.0f / s1r;
    uint32_t* out32 = (uint32_t*)attn_out;
    #pragma unroll
    for (int nt = 0; nt < 6; nt++) {
        int d = 8*nt + 2*tig;
        size_t i0 = ((size_t)(b*LL + qrow0) * 384 + h*48 + d) >> 1;
        size_t i1 = ((size_t)(b*LL + qrow1) * 384 + h*48 + d) >> 1;
        out32[i0] = packf(o[nt][0]*inv0, o[nt][1]*inv0);
        out32[i1] = packf(o[nt][2]*inv1, o[nt][3]*inv1);
    }
}

// ============================================================
// launch
// ============================================================
extern "C" void kernel_launch(void* const* d_in, const int* in_sizes, int n_in,
                              void* d_out, int out_size)
{
    (void)in_sizes; (void)n_in; (void)out_size;
    const float* x        = (const float*)d_in[0];
    const float* gamma    = (const float*)d_in[1];
    const float* beta     = (const float*)d_in[2];
    const float* Wq       = (const float*)d_in[3];
    const float* Wk       = (const float*)d_in[4];
    const float* Wv       = (const float*)d_in[5];
    const float* Wo       = (const float*)d_in[6];
    const float* bo       = (const float*)d_in[7];
    const float* rel_bias = (const float*)d_in[8];
    const float* fc1_w    = (const float*)d_in[9];
    const float* fc1_b    = (const float*)d_in[10];
    const float* fc2_w    = (const float*)d_in[11];
    const float* fc2_b    = (const float*)d_in[12];
    float* out = (float*)d_out;

    fp16 *tok, *attn, *ytokh, *u1, *w, *q16, *kh, *vh;
    float *vf, *ytok;
    cudaGetSymbolAddress((void**)&tok,   g_tok);
    cudaGetSymbolAddress((void**)&q16,   g_q16);
    cudaGetSymbolAddress((void**)&kh,    g_kh);
    cudaGetSymbolAddress((void**)&vf,    g_vf);
    cudaGetSymbolAddress((void**)&vh,    g_vh);
    cudaGetSymbolAddress((void**)&attn,  g_attn);
    cudaGetSymbolAddress((void**)&ytok,  g_ytok);
    cudaGetSymbolAddress((void**)&ytokh, g_ytokh);
    cudaGetSymbolAddress((void**)&u1,    g_u1);
    cudaGetSymbolAddress((void**)&w,     g_w);

    const int M = MM;
    const int GEMM_SMEM = 30720;
    const int ATTN_SMEM = 28160;
    const int LN_SMEM   = 384*33*4;

    cudaFuncSetAttribute(ln_kernel, cudaFuncAttributeMaxDynamicSharedMemorySize, LN_SMEM);

    conv_all<<<(NW_TOTAL/4 + 255)/256, 256>>>(Wq, Wk, Wv, Wo, fc1_w, fc2_w, w);

    ln_kernel<<<dim3(LL/32, BB), 256, LN_SMEM>>>(x, gamma, beta, tok);

    gemm_f16<2><<<dim3(1152/64, M/128), 256, GEMM_SMEM>>>(tok, w+OFF_WQ, nullptr, vf,
                                               M, 1152, 384, nullptr, nullptr);

    v_prep<<<dim3(LL/64, BB*NHH), 256>>>(vf, vh);

    attn_mma<<<dim3(LL/128, BB*NHH), 256, ATTN_SMEM>>>(q16, kh, vh, rel_bias, attn);

    gemm_f16<3><<<dim3(384/64,  M/128), 256, GEMM_SMEM>>>(attn, w+OFF_WO, bo, ytok,
                                               M, 384, 384, x, ytokh);
    gemm_f16<1><<<dim3(1536/64, M/128), 256, GEMM_SMEM>>>(ytokh, w+OFF_FC1, fc1_b, nullptr,
                                               M, 1536, 384, nullptr, u1);
    gemm_f16<4><<<dim3(384/64,  M/128), 256, GEMM_SMEM>>>(u1, w+OFF_FC2, fc2_b, out,
                                               M, 384, 1536, ytok, nullptr);
}

// round 17
// speedup vs baseline: 3.4353x; 1.0245x over previous
#include <cuda_runtime.h>
#include <cuda_fp16.h>
#include <math.h>
#include <stdint.h>

// ---- problem constants ----
#define BB   8
#define CC   384
#define LL   1024
#define MM   (BB*LL)
#define NHH  8
#define DKK  48
#define DVV  48
#define CFF_ 1536
#define NBIAS_ 3969
#define LN_EPS_ 1e-5f

typedef __half fp16;

// ---- scratch ----
__device__ __align__(16) fp16  g_tok [MM*CC];
__device__ __align__(16) fp16  g_q16[MM*CC];          // [bh][l][d]
__device__ __align__(16) fp16  g_kh [MM*CC];          // [bh][key][d]
__device__ __align__(16) fp16  g_vh [MM*CC];          // [bh][key][d] (row-major, trans-ldmatrix)
__device__ __align__(16) fp16  g_attn[MM*CC];
__device__ __align__(16) float g_ytok[MM*CC];
__device__ __align__(16) fp16  g_ytokh[MM*CC];
__device__ __align__(16) fp16  g_u1[MM*CFF_];

#define OFF_WQ  0
#define OFF_WO  442368
#define OFF_FC1 589824
#define OFF_FC2 1179648
#define NW_TOTAL 1769472
__device__ __align__(16) fp16 g_w[NW_TOTAL];

// single-instruction fp16x2 pack (RN)
__device__ __forceinline__ uint32_t packf(float a, float b) {
    uint32_t r;
    asm("cvt.rn.f16x2.f32 %0, %1, %2;" : "=r"(r) : "f"(b), "f"(a));
    return r;
}
__device__ __forceinline__ uint32_t smem_u32(const void* p) {
    uint32_t a;
    asm("{ .reg .u64 t; cvta.to.shared.u64 t, %1; cvt.u32.u64 %0, t; }"
        : "=r"(a) : "l"(p));
    return a;
}
__device__ __forceinline__ void cp16(uint32_t saddr, const void* g) {
    asm volatile("cp.async.cg.shared.global [%0], [%1], 16;"
                 :: "r"(saddr), "l"(g) : "memory");
}
#define CP_COMMIT() asm volatile("cp.async.commit_group;" ::: "memory")
#define CP_WAIT1()  asm volatile("cp.async.wait_group 1;" ::: "memory")
#define CP_WAIT0()  asm volatile("cp.async.wait_group 0;" ::: "memory")

#define MMA_F16(c, a, b) \
    asm volatile("mma.sync.aligned.m16n8k16.row.col.f32.f16.f16.f32 " \
        "{%0,%1,%2,%3}, {%4,%5,%6,%7}, {%8,%9}, {%0,%1,%2,%3};" \
        : "+f"((c)[0]), "+f"((c)[1]), "+f"((c)[2]), "+f"((c)[3]) \
        : "r"((a)[0]), "r"((a)[1]), "r"((a)[2]), "r"((a)[3]), \
          "r"((b)[0]), "r"((b)[1]))

#define LDSM4(r, addr) \
    asm volatile("ldmatrix.sync.aligned.m8n8.x4.shared.b16 {%0,%1,%2,%3}, [%4];" \
        : "=r"((r)[0]), "=r"((r)[1]), "=r"((r)[2]), "=r"((r)[3]) : "r"(addr))

#define LDSM4T(r, addr) \
    asm volatile("ldmatrix.sync.aligned.m8n8.x4.trans.shared.b16 {%0,%1,%2,%3}, [%4];" \
        : "=r"((r)[0]), "=r"((r)[1]), "=r"((r)[2]), "=r"((r)[3]) : "r"(addr))

// ============================================================
// Merged weight fp16 conversion (vectorized)
// ============================================================
__global__ void conv_all(const float* __restrict__ Wq, const float* __restrict__ Wk,
                         const float* __restrict__ Wv, const float* __restrict__ Wo,
                         const float* __restrict__ f1, const float* __restrict__ f2,
                         fp16* __restrict__ w)
{
    int i4 = blockIdx.x * 256 + threadIdx.x;
    if (i4 >= NW_TOTAL/4) return;
    int i = i4 * 4;
    const float* src; int off;
    if (i < OFF_WO) {
        int m = i / 147456; off = i - m * 147456;
        src = (m == 0) ? Wq : (m == 1) ? Wk : Wv;
    } else if (i < OFF_FC1) { src = Wo; off = i - OFF_WO; }
    else if (i < OFF_FC2)   { src = f1; off = i - OFF_FC1; }
    else                    { src = f2; off = i - OFF_FC2; }
    float4 p = *(const float4*)&src[off];
    uint2 o;
    o.x = packf(p.x, p.y);
    o.y = packf(p.z, p.w);
    *(uint2*)&w[i] = o;
}

// ============================================================
// LayerNorm (unchanged)
// ============================================================
__global__ void ln_kernel(const float* __restrict__ x,
                          const float* __restrict__ gamma,
                          const float* __restrict__ beta,
                          fp16* __restrict__ tok)
{
    extern __shared__ __align__(16) float sbuf[];   // [384][33]
    __shared__ float redS [8][32];
    __shared__ float redS2[8][32];
    __shared__ float s_mu[32], s_inv[32];

    const int b  = blockIdx.y;
    const int l0 = blockIdx.x * 32;
    const int tid = threadIdx.x;
    const int lane = tid & 31;
    const int cy   = tid >> 5;

    for (int e = tid; e < CC*32; e += 256) {
        int c = e >> 5, t = e & 31;
        sbuf[c*33 + t] = x[((size_t)b*CC + c)*LL + l0 + t];
    }
    __syncthreads();

    float s = 0.f, s2 = 0.f;
    for (int c = cy; c < CC; c += 8) {
        float v = sbuf[c*33 + lane];
        s += v; s2 += v*v;
    }
    redS[cy][lane] = s; redS2[cy][lane] = s2;
    __syncthreads();
    if (cy == 0) {
        float ts = 0.f, ts2 = 0.f;
        #pragma unroll
        for (int i = 0; i < 8; i++) { ts += redS[i][lane]; ts2 += redS2[i][lane]; }
        float mu = ts * (1.0f/384.0f);
        float var = ts2 * (1.0f/384.0f) - mu*mu;
        s_mu[lane] = mu;
        s_inv[lane] = rsqrtf(var + LN_EPS_);
    }
    __syncthreads();

    uint32_t* tok32 = (uint32_t*)tok;
    for (int e = tid; e < CC*16; e += 256) {
        int t = e / 192, cp = e - t*192;
        int c = 2*cp;
        float mu = s_mu[t], inv = s_inv[t];
        float v0 = (sbuf[c*33 + t]     - mu) * inv * gamma[c]     + beta[c];
        float v1 = (sbuf[(c+1)*33 + t] - mu) * inv * gamma[c+1]   + beta[c+1];
        tok32[(((size_t)b*LL + l0 + t)*CC + c) >> 1] = packf(v0, v1);
    }
}

// ============================================================
// fp16 warp-MMA GEMM, double-buffered smem + ldmatrix fragment loads.
// MODE 2: fused QKV -> q,k,v all packed fp16 [bh][l|key][d].
// ============================================================
template<int MODE>
__global__ __launch_bounds__(256)
void gemm_f16(const fp16* __restrict__ A,
              const fp16* __restrict__ W,
              const float* __restrict__ bias,
              float* __restrict__ Out,
              int M, int N, int K,
              const float* __restrict__ aux,
              fp16* __restrict__ outH)
{
    extern __shared__ __align__(16) uint32_t dsm[];
    const uint32_t sbase = smem_u32(dsm);

    const int tid  = threadIdx.x;
    const int m0   = blockIdx.y * 128;
    const int n0   = blockIdx.x * 64;
    const int warp = tid >> 5, lane = tid & 31;
    const int wm   = (warp >> 1) * 32;
    const int wn   = (warp & 1) * 32;
    const int gk   = lane & 3;
    const int gr   = lane >> 2;

    const int j  = lane >> 3;
    const int rl = lane & 7;
    const uint32_t aoff0 = ((uint32_t)(wm + (j&1)*8 + rl)*20 + (j>>1)*4)*4;
    const uint32_t aoff1 = aoff0 + 16*20*4;
    const uint32_t boff0 = 2560*4 + ((uint32_t)(wn + (j>>1)*8 + rl)*20 + (j&1)*4)*4;
    const uint32_t boff1 = boff0 + 16*20*4;

    const int ar = tid >> 1, ak = (tid & 1) * 16;
    const int br = tid >> 2, bk = (tid & 3) * 8;

    const fp16* Ap = A + (size_t)(m0 + ar) * K + ak;
    const fp16* Bp = W + (size_t)(n0 + br) * K + bk;

    uint4 pa0 = *(const uint4*)Ap;
    uint4 pa1 = *(const uint4*)(Ap + 8);
    uint4 pb  = *(const uint4*)Bp;

    float acc[2][4][4];
    #pragma unroll
    for (int mi = 0; mi < 2; mi++)
        #pragma unroll
        for (int nj = 0; nj < 4; nj++)
            #pragma unroll
            for (int r = 0; r < 4; r++) acc[mi][nj][r] = 0.f;

    const int acol = (tid & 1) * 8;
    const int bcol = (tid & 3) * 4;

    {
        uint32_t* sA = dsm;
        uint32_t* sB = dsm + 2560;
        *(uint4*)&sA[ar*20 + acol]     = pa0;
        *(uint4*)&sA[ar*20 + acol + 4] = pa1;
        *(uint4*)&sB[br*20 + bcol]     = pb;
    }
    __syncthreads();

    int stage = 0;
    for (int k0 = 0; k0 < K; k0 += 32) {
        const bool more = (k0 + 32 < K);
        if (more) {
            Ap += 32; Bp += 32;
            pa0 = *(const uint4*)Ap;
            pa1 = *(const uint4*)(Ap + 8);
            pb  = *(const uint4*)Bp;
        }

        const uint32_t sstg = sbase + stage*15360;

        #pragma unroll
        for (int ks = 0; ks < 2; ks++) {
            const uint32_t kb = ks*32;
            uint32_t a0[4], a1[4], b0[4], b1[4];
            LDSM4(a0, sstg + aoff0 + kb);
            LDSM4(a1, sstg + aoff1 + kb);
            LDSM4(b0, sstg + boff0 + kb);
            LDSM4(b1, sstg + boff1 + kb);
            MMA_F16(acc[0][0], a0, b0);      MMA_F16(acc[1][0], a1, b0);
            MMA_F16(acc[0][1], a0, &b0[2]);  MMA_F16(acc[1][1], a1, &b0[2]);
            MMA_F16(acc[0][2], a0, b1);      MMA_F16(acc[1][2], a1, b1);
            MMA_F16(acc[0][3], a0, &b1[2]);  MMA_F16(acc[1][3], a1, &b1[2]);
        }

        if (more) {
            uint32_t* nA = dsm + (stage^1)*3840;
            uint32_t* nB = nA + 2560;
            *(uint4*)&nA[ar*20 + acol]     = pa0;
            *(uint4*)&nA[ar*20 + acol + 4] = pa1;
            *(uint4*)&nB[br*20 + bcol]     = pb;
            stage ^= 1;
            __syncthreads();
        }
    }

    if (MODE == 2) {
        uint32_t* q32 = (uint32_t*)g_q16;
        uint32_t* k32 = (uint32_t*)g_kh;
        uint32_t* v32 = (uint32_t*)g_vh;
        #pragma unroll
        for (int mi = 0; mi < 2; mi++) {
            #pragma unroll
            for (int nj = 0; nj < 4; nj++) {
                int c0  = n0 + wn + nj*8 + 2*gk;
                int mat = c0 / 384;
                int cm  = c0 - mat * 384;
                int h = cm / 48, d0 = cm % 48;
                uint32_t* dst = (mat == 0) ? q32 : (mat == 1) ? k32 : v32;
                #pragma unroll
                for (int half = 0; half < 2; half++) {
                    int row = m0 + wm + mi*16 + gr + (half ? 8 : 0);
                    int b = row >> 10, l = row & 1023;
                    int bh = b*8 + h;
                    float v0 = acc[mi][nj][half*2 + 0];
                    float v1 = acc[mi][nj][half*2 + 1];
                    size_t ei = ((size_t)bh*1024 + l)*48 + d0;
                    dst[ei >> 1] = packf(v0, v1);
                }
            }
        }
        return;
    }

    #pragma unroll
    for (int mi = 0; mi < 2; mi++) {
        #pragma unroll
        for (int nj = 0; nj < 4; nj++) {
            #pragma unroll
            for (int r = 0; r < 4; r++) {
                int row = m0 + wm + mi*16 + gr + ((r & 2) ? 8 : 0);
                int col = n0 + wn + nj*8 + 2*gk + (r & 1);
                int b = row >> 10, l = row & 1023;
                float v = acc[mi][nj][r] + (bias ? bias[col] : 0.f);
                if (MODE == 3) {
                    v += aux[(size_t)(b*384 + col) * 1024 + l];
                    size_t idx = (size_t)row * 384 + col;
                    Out[idx] = v;
                    outH[idx] = __float2half(v);
                } else if (MODE == 1) {
                    v = 0.5f * v * (1.0f + erff(v * 0.70710678118654752f));
                    outH[(size_t)row * N + col] = __float2half(v);
                } else { // MODE 4
                    Out[(size_t)(b*384 + col) * 1024 + l] =
                        v + aux[(size_t)row * 384 + col];
                }
            }
        }
    }
}

// ============================================================
// FA2 fp16 attention: cp.async K/V double-buffer (both [key][d]),
// bias in smem, ldmatrix K loads + ldmatrix.trans V loads.
// ============================================================
#define AT_STAGE_U32 3584          // K 64x28 + V 64x28
#define AT_K_OFF     0
#define AT_V_OFF     1792

__global__ __launch_bounds__(256, 2)
void attn_mma(const fp16* __restrict__ q16,
              const fp16* __restrict__ khg,
              const fp16* __restrict__ vhg,
              const float* __restrict__ rel_bias,
              fp16* __restrict__ attn_out)
{
    extern __shared__ __align__(16) uint32_t asm_[];
    __shared__ float sBias[NBIAS_];

    const int b  = blockIdx.y >> 3;
    const int h  = blockIdx.y & 7;
    const int bh = b*8 + h;
    const int q0 = blockIdx.x * 128;
    const int tid  = threadIdx.x;
    const int warp = tid >> 5, lane = tid & 31;
    const int gid  = lane >> 2;
    const int tig  = lane & 3;

    const uint32_t* qbase32 = (const uint32_t*)(q16 + (size_t)bh * LL * 48);
    const uint4* kh4 = (const uint4*)(khg + (size_t)bh * LL * 48);
    const uint4* vh4 = (const uint4*)(vhg + (size_t)bh * LL * 48);
    const float* biasrow = rel_bias + (size_t)h * NBIAS_;

    const uint32_t sbase = smem_u32(asm_);

    for (int e = tid; e < NBIAS_; e += 256) sBias[e] = biasrow[e];

    const int j  = lane >> 3;
    const int rl = lane & 7;
    // K (non-trans): tile tp covers keys 16tp..+16, dp halves by j
    uint32_t koff[4];
    #pragma unroll
    for (int tp = 0; tp < 4; tp++)
        koff[tp] = ((uint32_t)(16*tp + (j>>1)*8 + rl)*28 + (j&1)*4)*4;
    // V (trans): per-lane row/col base; full addr depends on kp and d-group g
    const uint32_t vrow = (uint32_t)((j&1)*8 + rl);
    const uint32_t vcol = (uint32_t)((j>>1)*4);

    const int qrow0 = q0 + warp*16 + gid;
    const int qrow1 = qrow0 + 8;
    const int ly0 = qrow0 >> 5, lx0 = qrow0 & 31;
    const int ly1 = qrow1 >> 5, lx1 = qrow1 & 31;

    uint32_t qf[3][4];
    #pragma unroll
    for (int kp = 0; kp < 3; kp++) {
        int d0 = 16*kp + 2*tig;
        #pragma unroll
        for (int rr = 0; rr < 2; rr++) {
            int row = rr ? qrow1 : qrow0;
            qf[kp][rr]   = qbase32[((size_t)row*48 + d0) >> 1];
            qf[kp][rr+2] = qbase32[((size_t)row*48 + d0 + 8) >> 1];
        }
    }

    float m0r = -1e30f, m1r = -1e30f, s0r = 0.f, s1r = 0.f;
    float o[6][4];
    #pragma unroll
    for (int nt = 0; nt < 6; nt++)
        #pragma unroll
        for (int r = 0; r < 4; r++) o[nt][r] = 0.f;

    auto issue = [&](int mc, int buf) {
        uint32_t kb = sbase + (buf*AT_STAGE_U32 + AT_K_OFF)*4;
        uint32_t vb = sbase + (buf*AT_STAGE_U32 + AT_V_OFF)*4;
        for (int e = tid; e < 384; e += 256) {
            int r = e / 6, jj = e - r*6;
            cp16(kb + (r*28 + 4*jj)*4, kh4 + (size_t)(mc + r)*6 + jj);
        }
        for (int e = tid; e < 384; e += 256) {
            int r = e / 6, jj = e - r*6;
            cp16(vb + (r*28 + 4*jj)*4, vh4 + (size_t)(mc + r)*6 + jj);
        }
    };

    issue(0, 0);
    CP_COMMIT();

    for (int ic = 0; ic < 16; ic++) {
        const int mc = ic * 64;
        const int buf = ic & 1;

        if (ic + 1 < 16) {
            issue(mc + 64, buf ^ 1);
            CP_COMMIT();
            CP_WAIT1();
        } else {
            CP_WAIT0();
        }
        __syncthreads();

        const uint32_t bufoff = sbase + buf*(AT_STAGE_U32*4);

        // ---- S = Q K^T ----
        float sc[8][4];
        #pragma unroll
        for (int t = 0; t < 8; t++)
            #pragma unroll
            for (int r = 0; r < 4; r++) sc[t][r] = 0.f;

        #pragma unroll
        for (int kp = 0; kp < 3; kp++) {
            #pragma unroll
            for (int tp = 0; tp < 4; tp++) {
                uint32_t kk[4];
                LDSM4(kk, bufoff + koff[tp] + kp*32);
                MMA_F16(sc[2*tp],     qf[kp], kk);
                MMA_F16(sc[2*tp + 1], qf[kp], &kk[2]);
            }
        }

        // ---- bias + row max ----
        float rm0 = -1e30f, rm1 = -1e30f;
        #pragma unroll
        for (int t = 0; t < 8; t++) {
            int ma = mc + 8*t + 2*tig, mb = ma + 1;
            int may = ma >> 5, max_ = ma & 31;
            int mby = mb >> 5, mbx = mb & 31;
            sc[t][0] += sBias[(may - ly0 + 32)*32 + (max_ - lx0 + 32)];
            sc[t][1] += sBias[(mby - ly0 + 32)*32 + (mbx - lx0 + 32)];
            sc[t][2] += sBias[(may - ly1 + 32)*32 + (max_ - lx1 + 32)];
            sc[t][3] += sBias[(mby - ly1 + 32)*32 + (mbx - lx1 + 32)];
            rm0 = fmaxf(rm0, fmaxf(sc[t][0], sc[t][1]));
            rm1 = fmaxf(rm1, fmaxf(sc[t][2], sc[t][3]));
        }
        rm0 = fmaxf(rm0, __shfl_xor_sync(0xffffffffu, rm0, 1));
        rm0 = fmaxf(rm0, __shfl_xor_sync(0xffffffffu, rm0, 2));
        rm1 = fmaxf(rm1, __shfl_xor_sync(0xffffffffu, rm1, 1));
        rm1 = fmaxf(rm1, __shfl_xor_sync(0xffffffffu, rm1, 2));

        float nm0 = fmaxf(m0r, rm0), nm1 = fmaxf(m1r, rm1);
        float al0 = __expf(m0r - nm0), al1 = __expf(m1r - nm1);
        m0r = nm0; m1r = nm1;

        #pragma unroll
        for (int nt = 0; nt < 6; nt++) {
            o[nt][0] *= al0; o[nt][1] *= al0;
            o[nt][2] *= al1; o[nt][3] *= al1;
        }

        // ---- fused exp/pack + PV (V via ldmatrix.trans) ----
        float ps0 = 0.f, ps1 = 0.f;
        #pragma unroll
        for (int kp = 0; kp < 4; kp++) {
            uint32_t pf[4];
            #pragma unroll
            for (int tt = 0; tt < 2; tt++) {
                int t = 2*kp + tt;
                float p0 = __expf(sc[t][0] - nm0);
                float p1 = __expf(sc[t][1] - nm0);
                float p2 = __expf(sc[t][2] - nm1);
                float p3 = __expf(sc[t][3] - nm1);
                ps0 += p0 + p1; ps1 += p2 + p3;
                pf[2*tt]   = packf(p0, p1);
                pf[2*tt+1] = packf(p2, p3);
            }
            const uint32_t vrowoff = bufoff + AT_V_OFF*4
                                   + ((16*kp + vrow)*28 + vcol)*4;
            #pragma unroll
            for (int g = 0; g < 3; g++) {
                uint32_t vv[4];
                LDSM4T(vv, vrowoff + g*8*4);
                MMA_F16(o[2*g],     pf, vv);
                MMA_F16(o[2*g + 1], pf, &vv[2]);
            }
        }
        ps0 += __shfl_xor_sync(0xffffffffu, ps0, 1);
        ps0 += __shfl_xor_sync(0xffffffffu, ps0, 2);
        ps1 += __shfl_xor_sync(0xffffffffu, ps1, 1);
        ps1 += __shfl_xor_sync(0xffffffffu, ps1, 2);
        s0r = s0r * al0 + ps0;
        s1r = s1r * al1 + ps1;

        __syncthreads();
    }

    float inv0 = 1.0f / s0r, inv1 = 1.0f / s1r;
    uint32_t* out32 = (uint32_t*)attn_out;
    #pragma unroll
    for (int nt = 0; nt < 6; nt++) {
        int d = 8*nt + 2*tig;
        size_t i0 = ((size_t)(b*LL + qrow0) * 384 + h*48 + d) >> 1;
        size_t i1 = ((size_t)(b*LL + qrow1) * 384 + h*48 + d) >> 1;
        out32[i0] = packf(o[nt][0]*inv0, o[nt][1]*inv0);
        out32[i1] = packf(o[nt][2]*inv1, o[nt][3]*inv1);
    }
}

// ============================================================
// launch
// ============================================================
extern "C" void kernel_launch(void* const* d_in, const int* in_sizes, int n_in,
                              void* d_out, int out_size)
{
    (void)in_sizes; (void)n_in; (void)out_size;
    const float* x        = (const float*)d_in[0];
    const float* gamma    = (const float*)d_in[1];
    const float* beta     = (const float*)d_in[2];
    const float* Wq       = (const float*)d_in[3];
    const float* Wk       = (const float*)d_in[4];
    const float* Wv       = (const float*)d_in[5];
    const float* Wo       = (const float*)d_in[6];
    const float* bo       = (const float*)d_in[7];
    const float* rel_bias = (const float*)d_in[8];
    const float* fc1_w    = (const float*)d_in[9];
    const float* fc1_b    = (const float*)d_in[10];
    const float* fc2_w    = (const float*)d_in[11];
    const float* fc2_b    = (const float*)d_in[12];
    float* out = (float*)d_out;

    fp16 *tok, *attn, *ytokh, *u1, *w, *q16, *kh, *vh;
    float *ytok;
    cudaGetSymbolAddress((void**)&tok,   g_tok);
    cudaGetSymbolAddress((void**)&q16,   g_q16);
    cudaGetSymbolAddress((void**)&kh,    g_kh);
    cudaGetSymbolAddress((void**)&vh,    g_vh);
    cudaGetSymbolAddress((void**)&attn,  g_attn);
    cudaGetSymbolAddress((void**)&ytok,  g_ytok);
    cudaGetSymbolAddress((void**)&ytokh, g_ytokh);
    cudaGetSymbolAddress((void**)&u1,    g_u1);
    cudaGetSymbolAddress((void**)&w,     g_w);

    const int M = MM;
    const int GEMM_SMEM = 30720;
    const int ATTN_SMEM = 28672;    // 2 stages x 14336 B
    const int LN_SMEM   = 384*33*4;

    cudaFuncSetAttribute(ln_kernel, cudaFuncAttributeMaxDynamicSharedMemorySize, LN_SMEM);

    conv_all<<<(NW_TOTAL/4 + 255)/256, 256>>>(Wq, Wk, Wv, Wo, fc1_w, fc2_w, w);

    ln_kernel<<<dim3(LL/32, BB), 256, LN_SMEM>>>(x, gamma, beta, tok);

    gemm_f16<2><<<dim3(1152/64, M/128), 256, GEMM_SMEM>>>(tok, w+OFF_WQ, nullptr, nullptr,
                                               M, 1152, 384, nullptr, nullptr);

    attn_mma<<<dim3(LL/128, BB*NHH), 256, ATTN_SMEM>>>(q16, kh, vh, rel_bias, attn);

    gemm_f16<3><<<dim3(384/64,  M/128), 256, GEMM_SMEM>>>(attn, w+OFF_WO, bo, ytok,
                                               M, 384, 384, x, ytokh);
    gemm_f16<1><<<dim3(1536/64, M/128), 256, GEMM_SMEM>>>(ytokh, w+OFF_FC1, fc1_b, nullptr,
                                               M, 1536, 384, nullptr, u1);
    gemm_f16<4><<<dim3(384/64,  M/128), 256, GEMM_SMEM>>>(u1, w+OFF_FC2, fc2_b, out,
                                               M, 384, 1536, ytok, nullptr);
}